// round 10
// baseline (speedup 1.0000x reference)
#include <cuda_runtime.h>
#include <math.h>

#define HID 32
#define MAXN 10240
#define MAXSEF 1100000

// device scratch (no allocs allowed)
__device__ __align__(16) float g_A[2][MAXN * HID];  // z @ M_w[0:32], dbl-buffered
__device__ float g_Bc[MAXN * HID];    // z @ M_w[32:64] + M_b
__device__ float g_z[MAXN * HID];     // current z
__device__ __align__(16) int2 g_pair[MAXSEF];  // (src, ef bits) [n][k], padded
__device__ float g_blockmax[8 * 1024];

// ---------------------------------------------------------------------------
// Prologue: re-lay (src, edge_feat) into per-node int2 pairs, padded to KS8
// (multiple of 8) with duplicates of edge 0 (idempotent under max).
// dst[e] == e % N.
// ---------------------------------------------------------------------------
__global__ void k_prep(const float* __restrict__ edges,
                       const int* __restrict__ src,
                       int N, int E, int Kc, int KS8, int Erem) {
    int o = blockIdx.x * blockDim.x + threadIdx.x;
    if (o >= N * KS8) return;
    int n = o / KS8, k = o - n * KS8;
    int kn = Kc + (n < Erem ? 1 : 0);
    int e = (k < kn) ? (k * N + n) : n;   // pad: duplicate edge k=0
    int s = __ldg(src + e);
    float f = __ldg(edges + (long)s * N + n);
    g_pair[o] = make_int2(s, __float_as_int(f));
}

// ---------------------------------------------------------------------------
// Init kernel: z0 = enc([states0, 0, pri]); A0 -> parity 0; Bc0; preds[0].
// Warp handles 2 nodes, lane = dim j. Grid: ceil(N/16).
// ---------------------------------------------------------------------------
__global__ void __launch_bounds__(256) k_init(
        const float* __restrict__ states0, const float* __restrict__ pri,
        const float* __restrict__ encw, const float* __restrict__ encb,
        const float* __restrict__ Mw,   const float* __restrict__ Mb,
        float* __restrict__ out, int N) {
    __shared__ float s_Mw[64 * HID];
    __shared__ __align__(8) float s_zs[HID][18];
    int tid = threadIdx.x;
    for (int i = tid; i < 64 * HID; i += 256) s_Mw[i] = Mw[i];
    __syncthreads();

    int w = tid >> 5, j = tid & 31, qb = w * 2;
    int n0 = blockIdx.x * 16 + qb;
    if (n0 >= N) return;
    const float2 st2 = *(const float2*)(states0 + n0);
    const float2 p2  = *(const float2*)(pri + n0);
    float eb = __ldg(encb + j);
    float w0 = __ldg(encw + j), w33 = __ldg(encw + 33 * HID + j);
    float z0 = fmaf(st2.x, w0, fmaf(p2.x, w33, eb));
    float z1 = fmaf(st2.y, w0, fmaf(p2.y, w33, eb));
    if (j < 2) out[n0 + j] = (j == 0) ? st2.x : st2.y;

    s_zs[j][qb + 0] = z0; s_zs[j][qb + 1] = z1;
    __syncwarp();
    float A0 = 0, A1 = 0, B0 = 0, B1 = 0;
    #pragma unroll
    for (int i = 0; i < HID; i++) {
        float wa = s_Mw[i * HID + j], wb = s_Mw[(HID + i) * HID + j];
        float2 zq = *(const float2*)&s_zs[i][qb];
        A0 = fmaf(zq.x, wa, A0); B0 = fmaf(zq.x, wb, B0);
        A1 = fmaf(zq.y, wa, A1); B1 = fmaf(zq.y, wb, B1);
    }
    float mb = __ldg(Mb + j);
    int r = n0 * HID + j;
    g_z[r] = z0; g_z[r + HID] = z1;
    g_A[0][r] = A0; g_A[0][r + HID] = A1;
    g_Bc[r] = B0 + mb; g_Bc[r + HID] = B1 + mb;
}

// ---------------------------------------------------------------------------
// Fused step kernel: 8 warps, 2 nodes/warp -> 16 nodes/block, grid 625.
// Edge phase: lane-group float4 gathers, depth-2 software pipeline
// (pairs k+2 iters ahead, rows 1 iter ahead -> no exposed L2 round trips).
// ---------------------------------------------------------------------------
__global__ void __launch_bounds__(256) k_step(int step, int par,
        const float* __restrict__ pri,
        const float* __restrict__ encw, const float* __restrict__ encb,
        const float* __restrict__ Mw,   const float* __restrict__ Mb,
        const float* __restrict__ Uw,   const float* __restrict__ Ub,
        const float* __restrict__ dnw,  const float* __restrict__ dnb,
        const float* __restrict__ duw,  const float* __restrict__ dub,
        const float* __restrict__ termw,const float* __restrict__ termb,
        float* __restrict__ out, int N, int T, int KS8) {
    __shared__ float s_encw[34 * HID];
    __shared__ float s_Uw[64 * HID];
    __shared__ float s_Mw[64 * HID];
    __shared__ float s_dnw[64];
    __shared__ float s_duw[65];
    __shared__ float s_termw[HID];
    __shared__ __align__(16) float s_um[8][64];
    __shared__ __align__(8) float s_zs[HID][18];
    __shared__ __align__(8) float s_us[HID][18];
    __shared__ float s_red[8];

    int tid = threadIdx.x;
    bool lastStep = (step >= T - 2);

    // weight prefetch into smem — latency hidden behind the edge phase
    if (!lastStep) {
        for (int i = tid; i < 34 * HID; i += 256) s_encw[i] = encw[i];
        for (int i = tid; i < 64 * HID; i += 256) s_Mw[i] = Mw[i];
    }
    for (int i = tid; i < 64 * HID; i += 256) s_Uw[i] = Uw[i];
    if (tid < 64) s_dnw[tid] = dnw[tid];
    if (tid < 65) s_duw[tid] = duw[tid];
    if (tid < HID) s_termw[tid] = termw[tid];

    int w = tid >> 5, j = tid & 31, qb = w * 2;
    int n0 = blockIdx.x * 16 + qb;
    bool active = (n0 < N);
    float locmax = -INFINITY;

    // ---------------- edge phase: pipelined lane-group vector gathers -------
    float z0 = 0.f, z1 = 0.f;
    if (active) {
        int r = n0 * HID + j;
        z0 = g_z[r]; z1 = g_z[r + HID];       // prefetch, overlaps gathers
        const float* __restrict__ Aold = g_A[par];
        int g = j >> 3, c4 = (j & 7) << 2;    // group 0..3, col base 4*(j&7)
        const float4 fw4 = *(const float4*)(Mw + 64 * HID + c4);
        #pragma unroll
        for (int qi = 0; qi < 2; qi++) {
            const int2* __restrict__ pp = g_pair + (long)(n0 + qi) * KS8 + g;
            float mx = -INFINITY, my = -INFINITY, mz = -INFINITY, mw2 = -INFINITY;
            if (KS8 >= 16) {
                // prologue: pairs for iters 0 and 1; rows for iter 0
                int2 p0 = __ldg(pp);
                int2 p1 = __ldg(pp + 4);
                int2 q0 = __ldg(pp + 8);
                int2 q1 = __ldg(pp + 12);
                float4 a0 = __ldg((const float4*)(Aold + (p0.x << 5) + c4));
                float4 a1 = __ldg((const float4*)(Aold + (p1.x << 5) + c4));
                int k = 0;
                for (; k + 16 < KS8; k += 8) {
                    int2 t0 = __ldg(pp + k + 16);          // pairs iter k+2
                    int2 t1 = __ldg(pp + k + 20);
                    float4 b0 = __ldg((const float4*)(Aold + (q0.x << 5) + c4));
                    float4 b1 = __ldg((const float4*)(Aold + (q1.x << 5) + c4));
                    float f0 = __int_as_float(p0.y);
                    float f1 = __int_as_float(p1.y);
                    mx  = fmaxf(mx,  fmaf(f0, fw4.x, a0.x));
                    my  = fmaxf(my,  fmaf(f0, fw4.y, a0.y));
                    mz  = fmaxf(mz,  fmaf(f0, fw4.z, a0.z));
                    mw2 = fmaxf(mw2, fmaf(f0, fw4.w, a0.w));
                    mx  = fmaxf(mx,  fmaf(f1, fw4.x, a1.x));
                    my  = fmaxf(my,  fmaf(f1, fw4.y, a1.y));
                    mz  = fmaxf(mz,  fmaf(f1, fw4.z, a1.z));
                    mw2 = fmaxf(mw2, fmaf(f1, fw4.w, a1.w));
                    p0 = q0; p1 = q1; q0 = t0; q1 = t1;
                    a0 = b0; a1 = b1;
                }
                // epilogue: iter k (a0/a1,p0,p1) + iter k+8 (q0,q1)
                float4 b0 = __ldg((const float4*)(Aold + (q0.x << 5) + c4));
                float4 b1 = __ldg((const float4*)(Aold + (q1.x << 5) + c4));
                float f0 = __int_as_float(p0.y);
                float f1 = __int_as_float(p1.y);
                mx  = fmaxf(mx,  fmaf(f0, fw4.x, a0.x));
                my  = fmaxf(my,  fmaf(f0, fw4.y, a0.y));
                mz  = fmaxf(mz,  fmaf(f0, fw4.z, a0.z));
                mw2 = fmaxf(mw2, fmaf(f0, fw4.w, a0.w));
                mx  = fmaxf(mx,  fmaf(f1, fw4.x, a1.x));
                my  = fmaxf(my,  fmaf(f1, fw4.y, a1.y));
                mz  = fmaxf(mz,  fmaf(f1, fw4.z, a1.z));
                mw2 = fmaxf(mw2, fmaf(f1, fw4.w, a1.w));
                f0 = __int_as_float(q0.y);
                f1 = __int_as_float(q1.y);
                mx  = fmaxf(mx,  fmaf(f0, fw4.x, b0.x));
                my  = fmaxf(my,  fmaf(f0, fw4.y, b0.y));
                mz  = fmaxf(mz,  fmaf(f0, fw4.z, b0.z));
                mw2 = fmaxf(mw2, fmaf(f0, fw4.w, b0.w));
                mx  = fmaxf(mx,  fmaf(f1, fw4.x, b1.x));
                my  = fmaxf(my,  fmaf(f1, fw4.y, b1.y));
                mz  = fmaxf(mz,  fmaf(f1, fw4.z, b1.z));
                mw2 = fmaxf(mw2, fmaf(f1, fw4.w, b1.w));
            } else {
                for (int k = 0; k < KS8; k += 4) {
                    int2 p0 = __ldg(pp + k);
                    float4 a0 = __ldg((const float4*)(Aold + (p0.x << 5) + c4));
                    float f0 = __int_as_float(p0.y);
                    mx  = fmaxf(mx,  fmaf(f0, fw4.x, a0.x));
                    my  = fmaxf(my,  fmaf(f0, fw4.y, a0.y));
                    mz  = fmaxf(mz,  fmaf(f0, fw4.z, a0.z));
                    mw2 = fmaxf(mw2, fmaf(f0, fw4.w, a0.w));
                }
            }
            // combine the 4 lane-groups (xor 8, xor 16)
            mx  = fmaxf(mx,  __shfl_xor_sync(0xffffffffu, mx, 8));
            my  = fmaxf(my,  __shfl_xor_sync(0xffffffffu, my, 8));
            mz  = fmaxf(mz,  __shfl_xor_sync(0xffffffffu, mz, 8));
            mw2 = fmaxf(mw2, __shfl_xor_sync(0xffffffffu, mw2, 8));
            mx  = fmaxf(mx,  __shfl_xor_sync(0xffffffffu, mx, 16));
            my  = fmaxf(my,  __shfl_xor_sync(0xffffffffu, my, 16));
            mz  = fmaxf(mz,  __shfl_xor_sync(0xffffffffu, mz, 16));
            mw2 = fmaxf(mw2, __shfl_xor_sync(0xffffffffu, mw2, 16));
            if (g == 0)
                *(float4*)&s_um[w][qi * 32 + c4] = make_float4(mx, my, mz, mw2);
        }
        __syncwarp();
    }
    __syncthreads();   // weights ready

    // ---------------- node phase (R5 layout) --------------------------------
    if (active) {
        int r = n0 * HID + j;
        float u0 = g_Bc[r]       + s_um[w][j];
        float u1 = g_Bc[r + HID] + s_um[w][32 + j];
        s_zs[j][qb + 0] = z0; s_zs[j][qb + 1] = z1;
        s_us[j][qb + 0] = u0; s_us[j][qb + 1] = u1;
        __syncwarp();
        float ub = __ldg(Ub + j);
        float nh0 = ub, nh1 = ub;
        #pragma unroll
        for (int i = 0; i < HID; i++) {
            float wz = s_Uw[i * HID + j], wu = s_Uw[(HID + i) * HID + j];
            float2 zq = *(const float2*)&s_zs[i][qb];
            float2 uq = *(const float2*)&s_us[i][qb];
            nh0 = fmaf(zq.x, wz, nh0); nh0 = fmaf(uq.x, wu, nh0);
            nh1 = fmaf(zq.y, wz, nh1); nh1 = fmaf(uq.y, wu, nh1);
        }
        float tw = s_termw[j], d1 = s_dnw[j], d2 = s_dnw[HID + j];
        float e1 = s_duw[j], e2 = s_duw[HID + j];
        float l0 = nh0 * tw, l1 = nh1 * tw;
        float qd0 = fmaf(nh0, d1, z0 * d2), qd1 = fmaf(nh1, d1, z1 * d2);
        float rd0 = fmaf(nh0, e1, z0 * e2), rd1 = fmaf(nh1, e1, z1 * e2);
        #pragma unroll
        for (int o = 16; o; o >>= 1) {
            l0  += __shfl_xor_sync(0xffffffffu, l0, o);
            l1  += __shfl_xor_sync(0xffffffffu, l1, o);
            qd0 += __shfl_xor_sync(0xffffffffu, qd0, o);
            qd1 += __shfl_xor_sync(0xffffffffu, qd1, o);
            rd0 += __shfl_xor_sync(0xffffffffu, rd0, o);
            rd1 += __shfl_xor_sync(0xffffffffu, rd1, o);
        }
        float tb = __ldg(termb);
        locmax = fmaxf(l0, l1) + tb;
        float db = __ldg(dnb), du0 = __ldg(dub), dw64 = s_duw[64];
        float nn0 = qd0 + db, nn1 = qd1 + db;
        float ns0 = fmaf(nn0, dw64, rd0 + du0);
        float ns1 = fmaf(nn1, dw64, rd1 + du0);
        if (j < 2) {
            float nsv = (j == 0) ? ns0 : ns1;
            float nnv = (j == 0) ? nn0 : nn1;
            out[(step + 1) * N + n0 + j] = nsv;                    // preds
            out[T * N + T + (n0 + j) * (T - 1) + step] = nnv;      // preds_nextnode
        }
        if (!lastStep) {
            s_zs[j][qb + 0] = nh0; s_zs[j][qb + 1] = nh1;
            __syncwarp();
            const float2 p2 = *(const float2*)(pri + n0);
            float eb = __ldg(encb + j);
            float w0 = s_encw[j], w33 = s_encw[33 * HID + j];
            float zn0 = fmaf(ns0, w0, fmaf(p2.x, w33, eb));
            float zn1 = fmaf(ns1, w0, fmaf(p2.y, w33, eb));
            #pragma unroll
            for (int i = 0; i < HID; i++) {
                float we = s_encw[(1 + i) * HID + j];
                float2 hq = *(const float2*)&s_zs[i][qb];
                zn0 = fmaf(hq.x, we, zn0); zn1 = fmaf(hq.y, we, zn1);
            }
            s_us[j][qb + 0] = zn0; s_us[j][qb + 1] = zn1;
            __syncwarp();
            float A0 = 0, A1 = 0, B0 = 0, B1 = 0;
            #pragma unroll
            for (int i = 0; i < HID; i++) {
                float wa = s_Mw[i * HID + j], wb = s_Mw[(HID + i) * HID + j];
                float2 zq = *(const float2*)&s_us[i][qb];
                A0 = fmaf(zq.x, wa, A0); B0 = fmaf(zq.x, wb, B0);
                A1 = fmaf(zq.y, wa, A1); B1 = fmaf(zq.y, wb, B1);
            }
            float mb = __ldg(Mb + j);
            float* __restrict__ Anew = g_A[par ^ 1];
            g_z[r] = zn0; g_z[r + HID] = zn1;
            Anew[r] = A0; Anew[r + HID] = A1;
            g_Bc[r] = B0 + mb; g_Bc[r + HID] = B1 + mb;
        }
    }

    if (j == 0) s_red[w] = active ? locmax : -INFINITY;
    __syncthreads();
    if (tid == 0) {
        float m = -INFINITY;
        #pragma unroll
        for (int ww = 0; ww < 8; ww++) m = fmaxf(m, s_red[ww]);
        g_blockmax[step * 1024 + blockIdx.x] = m;
    }
}

// ---------------------------------------------------------------------------
// Finalize: preds_stop[0]=0, preds_stop[t+1]=sigmoid(max_blocks blockmax[t])
// ---------------------------------------------------------------------------
__global__ void k_final(float* __restrict__ out, int N, int T, int nblocks) {
    __shared__ float s_red[256];
    int t = blockIdx.x;
    float m = -INFINITY;
    for (int b = threadIdx.x; b < nblocks; b += blockDim.x)
        m = fmaxf(m, g_blockmax[t * 1024 + b]);
    s_red[threadIdx.x] = m;
    __syncthreads();
    for (int s = 128; s; s >>= 1) {
        if (threadIdx.x < s)
            s_red[threadIdx.x] = fmaxf(s_red[threadIdx.x], s_red[threadIdx.x + s]);
        __syncthreads();
    }
    if (threadIdx.x == 0) {
        float v = s_red[0];
        out[T * N + 1 + t] = 1.0f / (1.0f + expf(-v));
        if (t == 0) out[T * N] = 0.0f;
    }
}

// ---------------------------------------------------------------------------
extern "C" void kernel_launch(void* const* d_in, const int* in_sizes, int n_in,
                              void* d_out, int out_size) {
    const float* states   = (const float*)d_in[0];
    const float* priority = (const float*)d_in[1];
    const float* edges    = (const float*)d_in[2];
    const int*   src      = (const int*)d_in[3];
    const float* enc_w    = (const float*)d_in[5];
    const float* enc_b    = (const float*)d_in[6];
    const float* M_w      = (const float*)d_in[7];
    const float* M_b      = (const float*)d_in[8];
    const float* U_w      = (const float*)d_in[9];
    const float* U_b      = (const float*)d_in[10];
    const float* dn_w     = (const float*)d_in[11];
    const float* dn_b     = (const float*)d_in[12];
    const float* du_w     = (const float*)d_in[13];
    const float* du_b     = (const float*)d_in[14];
    const float* term_w   = (const float*)d_in[15];
    const float* term_b   = (const float*)d_in[16];
    float* out = (float*)d_out;

    int N = in_sizes[1];
    int E = in_sizes[3];
    int T = in_sizes[0] / N;
    int Kc = E / N;
    int Erem = E - Kc * N;
    int KS = Kc + (Erem ? 1 : 0);
    int KS8 = (KS + 7) & ~7;          // pad to multiple of 8

    int ptotal = N * KS8;
    k_prep<<<(ptotal + 255) / 256, 256>>>(edges, src, N, E, Kc, KS8, Erem);

    int nb = (N + 15) / 16;
    k_init<<<nb, 256>>>(states, priority, enc_w, enc_b, M_w, M_b, out, N);

    for (int t = 0; t < T - 1; t++) {
        k_step<<<nb, 256>>>(t, t & 1, priority, enc_w, enc_b, M_w, M_b,
                            U_w, U_b, dn_w, dn_b, du_w, du_b,
                            term_w, term_b, out, N, T, KS8);
    }
    k_final<<<T - 1, 256>>>(out, N, T, nb);
}

// round 11
// speedup vs baseline: 1.0867x; 1.0867x over previous
#include <cuda_runtime.h>
#include <math.h>

#define HID 32
#define MAXN 10240
#define MAXSEF 1200000

// device scratch (no allocs allowed)
__device__ __align__(16) float g_A[2][MAXN * HID];  // z @ M_w[0:32], dbl-buffered
__device__ float g_Bc[MAXN * HID];    // z @ M_w[32:64] + M_b
__device__ float g_z[MAXN * HID];     // current z
__device__ __align__(16) int2 g_pair[MAXSEF];  // (src, ef bits) [n][k], padded
__device__ float g_blockmax[8 * 2048];

// ---------------------------------------------------------------------------
// Prologue: re-lay (src, edge_feat) into per-node int2 pairs, padded to KS16
// (multiple of 16) with duplicates of edge 0 (idempotent under max).
// dst[e] == e % N.
// ---------------------------------------------------------------------------
__global__ void k_prep(const float* __restrict__ edges,
                       const int* __restrict__ src,
                       int N, int E, int Kc, int KS16, int Erem) {
    int o = blockIdx.x * blockDim.x + threadIdx.x;
    if (o >= N * KS16) return;
    int n = o / KS16, k = o - n * KS16;
    int kn = Kc + (n < Erem ? 1 : 0);
    int e = (k < kn) ? (k * N + n) : n;   // pad: duplicate edge k=0
    int s = __ldg(src + e);
    float f = __ldg(edges + (long)s * N + n);
    g_pair[o] = make_int2(s, __float_as_int(f));
}

// ---------------------------------------------------------------------------
// Init kernel: z0 = enc([states0, 0, pri]); A0 -> parity 0; Bc0; preds[0].
// Warp handles 2 nodes, lane = dim j. Grid: ceil(N/16).
// ---------------------------------------------------------------------------
__global__ void __launch_bounds__(256) k_init(
        const float* __restrict__ states0, const float* __restrict__ pri,
        const float* __restrict__ encw, const float* __restrict__ encb,
        const float* __restrict__ Mw,   const float* __restrict__ Mb,
        float* __restrict__ out, int N) {
    __shared__ float s_Mw[64 * HID];
    __shared__ __align__(8) float s_zs[HID][18];
    int tid = threadIdx.x;
    for (int i = tid; i < 64 * HID; i += 256) s_Mw[i] = Mw[i];
    __syncthreads();

    int w = tid >> 5, j = tid & 31, qb = w * 2;
    int n0 = blockIdx.x * 16 + qb;
    if (n0 >= N) return;
    const float2 st2 = *(const float2*)(states0 + n0);
    const float2 p2  = *(const float2*)(pri + n0);
    float eb = __ldg(encb + j);
    float w0 = __ldg(encw + j), w33 = __ldg(encw + 33 * HID + j);
    float z0 = fmaf(st2.x, w0, fmaf(p2.x, w33, eb));
    float z1 = fmaf(st2.y, w0, fmaf(p2.y, w33, eb));
    if (j < 2) out[n0 + j] = (j == 0) ? st2.x : st2.y;

    s_zs[j][qb + 0] = z0; s_zs[j][qb + 1] = z1;
    __syncwarp();
    float A0 = 0, A1 = 0, B0 = 0, B1 = 0;
    #pragma unroll
    for (int i = 0; i < HID; i++) {
        float wa = s_Mw[i * HID + j], wb = s_Mw[(HID + i) * HID + j];
        float2 zq = *(const float2*)&s_zs[i][qb];
        A0 = fmaf(zq.x, wa, A0); B0 = fmaf(zq.x, wb, B0);
        A1 = fmaf(zq.y, wa, A1); B1 = fmaf(zq.y, wb, B1);
    }
    float mb = __ldg(Mb + j);
    int r = n0 * HID + j;
    g_z[r] = z0; g_z[r + HID] = z1;
    g_A[0][r] = A0; g_A[0][r + HID] = A1;
    g_Bc[r] = B0 + mb; g_Bc[r + HID] = B1 + mb;
}

// ---------------------------------------------------------------------------
// Fused step kernel: 16 warps, 8 nodes/block (2 warps per node, each half the
// edge list), grid 1250. Edge loop = R8 lane-group float4 gathers.
// ---------------------------------------------------------------------------
__global__ void __launch_bounds__(512, 3) k_step(int step, int par,
        const float* __restrict__ pri,
        const float* __restrict__ encw, const float* __restrict__ encb,
        const float* __restrict__ Mw,   const float* __restrict__ Mb,
        const float* __restrict__ Uw,   const float* __restrict__ Ub,
        const float* __restrict__ dnw,  const float* __restrict__ dnb,
        const float* __restrict__ duw,  const float* __restrict__ dub,
        const float* __restrict__ termw,const float* __restrict__ termb,
        float* __restrict__ out, int N, int T, int KS16) {
    __shared__ float s_encw[34 * HID];
    __shared__ float s_Uw[64 * HID];
    __shared__ float s_Mw[64 * HID];
    __shared__ float s_dnw[64];
    __shared__ float s_duw[65];
    __shared__ float s_termw[HID];
    __shared__ __align__(16) float s_um[16][HID];
    __shared__ float s_z[8][HID];
    __shared__ float s_u[8][HID];
    __shared__ float s_red[8];

    int tid = threadIdx.x;
    bool lastStep = (step >= T - 2);

    // weight prefetch into smem — latency hidden behind the edge phase
    if (!lastStep) {
        for (int i = tid; i < 34 * HID; i += 512) s_encw[i] = encw[i];
        for (int i = tid; i < 64 * HID; i += 512) s_Mw[i] = Mw[i];
    }
    for (int i = tid; i < 64 * HID; i += 512) s_Uw[i] = Uw[i];
    if (tid < 64) s_dnw[tid] = dnw[tid];
    if (tid < 65) s_duw[tid] = duw[tid];
    if (tid < HID) s_termw[tid] = termw[tid];

    int w = tid >> 5, j = tid & 31;
    int wn = w & 7, h = w >> 3;           // node-in-block, half index
    int n = blockIdx.x * 8 + wn;
    bool active = (n < N);
    int KH = KS16 >> 1;                   // edges per half (multiple of 8)
    float locmax = -INFINITY;

    // ---------------- edge phase: all 16 warps, half a node each ------------
    float z = 0.f;
    if (active) {
        if (h == 0) z = g_z[n * HID + j];  // node-phase warp prefetches z
        const float* __restrict__ Aold = g_A[par];
        int g = j >> 3, c4 = (j & 7) << 2; // group 0..3, col base 4*(j&7)
        const float4 fw4 = *(const float4*)(Mw + 64 * HID + c4);
        const int2* __restrict__ pp = g_pair + (long)n * KS16 + h * KH + g;
        float mx = -INFINITY, my = -INFINITY, mz = -INFINITY, mw2 = -INFINITY;
        #pragma unroll 2
        for (int k = 0; k < KH; k += 8) {
            int2 p0 = __ldg(pp + k);
            int2 p1 = __ldg(pp + k + 4);
            float4 a0 = __ldg((const float4*)(Aold + (p0.x << 5) + c4));
            float4 a1 = __ldg((const float4*)(Aold + (p1.x << 5) + c4));
            float f0 = __int_as_float(p0.y);
            float f1 = __int_as_float(p1.y);
            mx  = fmaxf(mx,  fmaf(f0, fw4.x, a0.x));
            my  = fmaxf(my,  fmaf(f0, fw4.y, a0.y));
            mz  = fmaxf(mz,  fmaf(f0, fw4.z, a0.z));
            mw2 = fmaxf(mw2, fmaf(f0, fw4.w, a0.w));
            mx  = fmaxf(mx,  fmaf(f1, fw4.x, a1.x));
            my  = fmaxf(my,  fmaf(f1, fw4.y, a1.y));
            mz  = fmaxf(mz,  fmaf(f1, fw4.z, a1.z));
            mw2 = fmaxf(mw2, fmaf(f1, fw4.w, a1.w));
        }
        // combine the 4 lane-groups (xor 8, xor 16)
        mx  = fmaxf(mx,  __shfl_xor_sync(0xffffffffu, mx, 8));
        my  = fmaxf(my,  __shfl_xor_sync(0xffffffffu, my, 8));
        mz  = fmaxf(mz,  __shfl_xor_sync(0xffffffffu, mz, 8));
        mw2 = fmaxf(mw2, __shfl_xor_sync(0xffffffffu, mw2, 8));
        mx  = fmaxf(mx,  __shfl_xor_sync(0xffffffffu, mx, 16));
        my  = fmaxf(my,  __shfl_xor_sync(0xffffffffu, my, 16));
        mz  = fmaxf(mz,  __shfl_xor_sync(0xffffffffu, mz, 16));
        mw2 = fmaxf(mw2, __shfl_xor_sync(0xffffffffu, mw2, 16));
        if (g == 0)
            *(float4*)&s_um[w][c4] = make_float4(mx, my, mz, mw2);
    }
    __syncthreads();   // halves + weights ready

    // ---------------- node phase: warps 0..7, one node each -----------------
    if (h == 0 && active) {
        int r = n * HID + j;
        float u = g_Bc[r] + fmaxf(s_um[wn][j], s_um[wn + 8][j]);
        s_z[wn][j] = z;
        s_u[wn][j] = u;
        __syncwarp();
        float nh = __ldg(Ub + j);
        #pragma unroll
        for (int i = 0; i < HID; i++) {
            nh = fmaf(s_z[wn][i], s_Uw[i * HID + j], nh);
            nh = fmaf(s_u[wn][i], s_Uw[(HID + i) * HID + j], nh);
        }
        float l  = nh * s_termw[j];
        float qd = fmaf(nh, s_dnw[j], z * s_dnw[HID + j]);
        float rd = fmaf(nh, s_duw[j], z * s_duw[HID + j]);
        #pragma unroll
        for (int o = 16; o; o >>= 1) {
            l  += __shfl_xor_sync(0xffffffffu, l, o);
            qd += __shfl_xor_sync(0xffffffffu, qd, o);
            rd += __shfl_xor_sync(0xffffffffu, rd, o);
        }
        locmax = l + __ldg(termb);
        float nn = qd + __ldg(dnb);
        float ns = fmaf(nn, s_duw[64], rd + __ldg(dub));
        if (j == 0) {
            out[(step + 1) * N + n] = ns;                  // preds
            out[T * N + T + n * (T - 1) + step] = nn;      // preds_nextnode
        }
        if (!lastStep) {
            s_u[wn][j] = nh;                               // nh broadcast slot
            __syncwarp();
            float pr = __ldg(pri + n);
            float zn = fmaf(ns, s_encw[j], fmaf(pr, s_encw[33 * HID + j], __ldg(encb + j)));
            #pragma unroll
            for (int i = 0; i < HID; i++)
                zn = fmaf(s_u[wn][i], s_encw[(1 + i) * HID + j], zn);
            s_z[wn][j] = zn;
            __syncwarp();
            float A = 0, B = 0;
            #pragma unroll
            for (int i = 0; i < HID; i++) {
                float zi = s_z[wn][i];
                A = fmaf(zi, s_Mw[i * HID + j], A);
                B = fmaf(zi, s_Mw[(HID + i) * HID + j], B);
            }
            float* __restrict__ Anew = g_A[par ^ 1];
            g_z[r] = zn;
            Anew[r] = A;
            g_Bc[r] = B + __ldg(Mb + j);
        }
    }

    if (h == 0 && j == 0) s_red[wn] = active ? locmax : -INFINITY;
    __syncthreads();
    if (tid == 0) {
        float m = -INFINITY;
        #pragma unroll
        for (int ww = 0; ww < 8; ww++) m = fmaxf(m, s_red[ww]);
        g_blockmax[step * 2048 + blockIdx.x] = m;
    }
}

// ---------------------------------------------------------------------------
// Finalize: preds_stop[0]=0, preds_stop[t+1]=sigmoid(max_blocks blockmax[t])
// ---------------------------------------------------------------------------
__global__ void k_final(float* __restrict__ out, int N, int T, int nblocks) {
    __shared__ float s_red[256];
    int t = blockIdx.x;
    float m = -INFINITY;
    for (int b = threadIdx.x; b < nblocks; b += blockDim.x)
        m = fmaxf(m, g_blockmax[t * 2048 + b]);
    s_red[threadIdx.x] = m;
    __syncthreads();
    for (int s = 128; s; s >>= 1) {
        if (threadIdx.x < s)
            s_red[threadIdx.x] = fmaxf(s_red[threadIdx.x], s_red[threadIdx.x + s]);
        __syncthreads();
    }
    if (threadIdx.x == 0) {
        float v = s_red[0];
        out[T * N + 1 + t] = 1.0f / (1.0f + expf(-v));
        if (t == 0) out[T * N] = 0.0f;
    }
}

// ---------------------------------------------------------------------------
extern "C" void kernel_launch(void* const* d_in, const int* in_sizes, int n_in,
                              void* d_out, int out_size) {
    const float* states   = (const float*)d_in[0];
    const float* priority = (const float*)d_in[1];
    const float* edges    = (const float*)d_in[2];
    const int*   src      = (const int*)d_in[3];
    const float* enc_w    = (const float*)d_in[5];
    const float* enc_b    = (const float*)d_in[6];
    const float* M_w      = (const float*)d_in[7];
    const float* M_b      = (const float*)d_in[8];
    const float* U_w      = (const float*)d_in[9];
    const float* U_b      = (const float*)d_in[10];
    const float* dn_w     = (const float*)d_in[11];
    const float* dn_b     = (const float*)d_in[12];
    const float* du_w     = (const float*)d_in[13];
    const float* du_b     = (const float*)d_in[14];
    const float* term_w   = (const float*)d_in[15];
    const float* term_b   = (const float*)d_in[16];
    float* out = (float*)d_out;

    int N = in_sizes[1];
    int E = in_sizes[3];
    int T = in_sizes[0] / N;
    int Kc = E / N;
    int Erem = E - Kc * N;
    int KS = Kc + (Erem ? 1 : 0);
    int KS16 = (KS + 15) & ~15;       // pad to multiple of 16 (two 8-mult halves)

    int ptotal = N * KS16;
    k_prep<<<(ptotal + 255) / 256, 256>>>(edges, src, N, E, Kc, KS16, Erem);

    int nbi = (N + 15) / 16;
    k_init<<<nbi, 256>>>(states, priority, enc_w, enc_b, M_w, M_b, out, N);

    int nb = (N + 7) / 8;   // 8 nodes per 512-thread block
    for (int t = 0; t < T - 1; t++) {
        k_step<<<nb, 512>>>(t, t & 1, priority, enc_w, enc_b, M_w, M_b,
                            U_w, U_b, dn_w, dn_b, du_w, du_b,
                            term_w, term_b, out, N, T, KS16);
    }
    k_final<<<T - 1, 256>>>(out, N, T, nb);
}

// round 12
// speedup vs baseline: 1.3100x; 1.2055x over previous
#include <cuda_runtime.h>
#include <math.h>

#define HID 32
#define MAXN 10240
#define MAXSEF 1100000

// device scratch (no allocs allowed)
__device__ __align__(16) float g_A[2][MAXN * HID];  // z @ M_w[0:32], dbl-buffered
__device__ __align__(16) int2 g_pair[MAXSEF];       // (src, ef bits) [n][k], padded
__device__ float g_blockmax[8 * 1024];
__device__ volatile unsigned g_gen;                 // barrier generation
__device__ unsigned g_cnt;                          // barrier arrival count

// ---------------------------------------------------------------------------
// Prologue: re-lay (src, edge_feat) into per-node int2 pairs, padded to KS8
// (multiple of 8) with duplicates of edge 0 (idempotent under max).
// dst[e] == e % N.
// ---------------------------------------------------------------------------
__global__ void k_prep(const float* __restrict__ edges,
                       const int* __restrict__ src,
                       int N, int E, int Kc, int KS8, int Erem) {
    int o = blockIdx.x * blockDim.x + threadIdx.x;
    if (o >= N * KS8) return;
    int n = o / KS8, k = o - n * KS8;
    int kn = Kc + (n < Erem ? 1 : 0);
    int e = (k < kn) ? (k * N + n) : n;   // pad: duplicate edge k=0
    int s = __ldg(src + e);
    float f = __ldg(edges + (long)s * N + n);
    g_pair[o] = make_int2(s, __float_as_int(f));
}

// ---------------------------------------------------------------------------
// Software grid barrier (all blocks resident by construction).
// __threadfence at entry publishes this block's A-writes AND invalidates the
// SM's L1 so post-barrier gathers see fresh data.
// ---------------------------------------------------------------------------
__device__ __forceinline__ void grid_sync_dev() {
    __threadfence();
    __syncthreads();
    if (threadIdx.x == 0) {
        unsigned gen = g_gen;
        if (atomicAdd(&g_cnt, 1u) == gridDim.x - 1u) {
            g_cnt = 0u;
            __threadfence();
            g_gen = gen + 1u;
        } else {
            while (g_gen == gen) __nanosleep(64);
        }
    }
    __syncthreads();
}

// ---------------------------------------------------------------------------
// Persistent fused kernel: init + all T-1 steps. 8 warps, 2 nodes/warp,
// 16 nodes/block, grid ceil(N/16) (all blocks resident: launch_bounds(256,5)).
// z and Bc live in registers across steps; weights in smem loaded once.
// ---------------------------------------------------------------------------
__global__ void __launch_bounds__(256, 5) k_all(
        const float* __restrict__ states0, const float* __restrict__ pri,
        const float* __restrict__ encw, const float* __restrict__ encb,
        const float* __restrict__ Mw,   const float* __restrict__ Mb,
        const float* __restrict__ Uw,   const float* __restrict__ Ub,
        const float* __restrict__ dnw,  const float* __restrict__ dnb,
        const float* __restrict__ duw,  const float* __restrict__ dub,
        const float* __restrict__ termw,const float* __restrict__ termb,
        float* __restrict__ out, int N, int T, int KS8) {
    __shared__ float s_encw[34 * HID];
    __shared__ float s_Uw[64 * HID];
    __shared__ float s_Mw[64 * HID];
    __shared__ float s_dnw[64];
    __shared__ float s_duw[65];
    __shared__ float s_termw[HID];
    __shared__ __align__(16) float s_um[8][64];
    __shared__ __align__(8) float s_zs[HID][18];
    __shared__ __align__(8) float s_us[HID][18];
    __shared__ float s_red[8];

    int tid = threadIdx.x;
    for (int i = tid; i < 34 * HID; i += 256) s_encw[i] = encw[i];
    for (int i = tid; i < 64 * HID; i += 256) s_Mw[i] = Mw[i];
    for (int i = tid; i < 64 * HID; i += 256) s_Uw[i] = Uw[i];
    if (tid < 64) s_dnw[tid] = dnw[tid];
    if (tid < 65) s_duw[tid] = duw[tid];
    if (tid < HID) s_termw[tid] = termw[tid];
    __syncthreads();

    int w = tid >> 5, j = tid & 31, qb = w * 2;
    int n0 = blockIdx.x * 16 + qb;
    bool active = (n0 < N);
    int g = j >> 3, c4 = (j & 7) << 2;      // lane group, col base
    const float4 fw4 = *(const float4*)(Mw + 64 * HID + c4);

    float z0 = 0.f, z1 = 0.f, bc0 = 0.f, bc1 = 0.f;

    // ---------------- init: z0/A0/Bc0 from states[0], preds[0] --------------
    if (active) {
        const float2 st2 = *(const float2*)(states0 + n0);
        const float2 p2  = *(const float2*)(pri + n0);
        float eb = __ldg(encb + j);
        float ew0 = s_encw[j], ew33 = s_encw[33 * HID + j];
        z0 = fmaf(st2.x, ew0, fmaf(p2.x, ew33, eb));
        z1 = fmaf(st2.y, ew0, fmaf(p2.y, ew33, eb));
        if (j < 2) out[n0 + j] = (j == 0) ? st2.x : st2.y;
        s_zs[j][qb + 0] = z0; s_zs[j][qb + 1] = z1;
        __syncwarp();
        float A0 = 0, A1 = 0, B0 = 0, B1 = 0;
        #pragma unroll
        for (int i = 0; i < HID; i++) {
            float wa = s_Mw[i * HID + j], wb = s_Mw[(HID + i) * HID + j];
            float2 zq = *(const float2*)&s_zs[i][qb];
            A0 = fmaf(zq.x, wa, A0); B0 = fmaf(zq.x, wb, B0);
            A1 = fmaf(zq.y, wa, A1); B1 = fmaf(zq.y, wb, B1);
        }
        float mb = __ldg(Mb + j);
        int r = n0 * HID + j;
        g_A[0][r] = A0; g_A[0][r + HID] = A1;
        bc0 = B0 + mb; bc1 = B1 + mb;
    }
    grid_sync_dev();

    // ---------------- T-1 fused steps ---------------------------------------
    for (int t = 0; t < T - 1; t++) {
        bool lastStep = (t == T - 2);
        float locmax = -INFINITY;

        if (active) {
            const float* __restrict__ Aold = g_A[t & 1];
            #pragma unroll
            for (int qi = 0; qi < 2; qi++) {
                const int2* __restrict__ pp = g_pair + (long)(n0 + qi) * KS8 + g;
                float mx = -INFINITY, my = -INFINITY, mz = -INFINITY, mw2 = -INFINITY;
                for (int k = 0; k < KS8; k += 8) {
                    int2 q0 = __ldg(pp + k);
                    int2 q1 = __ldg(pp + k + 4);
                    float4 a0 = __ldg((const float4*)(Aold + (q0.x << 5) + c4));
                    float4 a1 = __ldg((const float4*)(Aold + (q1.x << 5) + c4));
                    float f0 = __int_as_float(q0.y);
                    float f1 = __int_as_float(q1.y);
                    mx  = fmaxf(mx,  fmaf(f0, fw4.x, a0.x));
                    my  = fmaxf(my,  fmaf(f0, fw4.y, a0.y));
                    mz  = fmaxf(mz,  fmaf(f0, fw4.z, a0.z));
                    mw2 = fmaxf(mw2, fmaf(f0, fw4.w, a0.w));
                    mx  = fmaxf(mx,  fmaf(f1, fw4.x, a1.x));
                    my  = fmaxf(my,  fmaf(f1, fw4.y, a1.y));
                    mz  = fmaxf(mz,  fmaf(f1, fw4.z, a1.z));
                    mw2 = fmaxf(mw2, fmaf(f1, fw4.w, a1.w));
                }
                mx  = fmaxf(mx,  __shfl_xor_sync(0xffffffffu, mx, 8));
                my  = fmaxf(my,  __shfl_xor_sync(0xffffffffu, my, 8));
                mz  = fmaxf(mz,  __shfl_xor_sync(0xffffffffu, mz, 8));
                mw2 = fmaxf(mw2, __shfl_xor_sync(0xffffffffu, mw2, 8));
                mx  = fmaxf(mx,  __shfl_xor_sync(0xffffffffu, mx, 16));
                my  = fmaxf(my,  __shfl_xor_sync(0xffffffffu, my, 16));
                mz  = fmaxf(mz,  __shfl_xor_sync(0xffffffffu, mz, 16));
                mw2 = fmaxf(mw2, __shfl_xor_sync(0xffffffffu, mw2, 16));
                if (g == 0)
                    *(float4*)&s_um[w][qi * 32 + c4] = make_float4(mx, my, mz, mw2);
            }
            __syncwarp();

            // ---------------- node phase (z, Bc in registers) ---------------
            float u0 = bc0 + s_um[w][j];
            float u1 = bc1 + s_um[w][32 + j];
            s_zs[j][qb + 0] = z0; s_zs[j][qb + 1] = z1;
            s_us[j][qb + 0] = u0; s_us[j][qb + 1] = u1;
            __syncwarp();
            float ub = __ldg(Ub + j);
            float nh0 = ub, nh1 = ub;
            #pragma unroll
            for (int i = 0; i < HID; i++) {
                float wz = s_Uw[i * HID + j], wu = s_Uw[(HID + i) * HID + j];
                float2 zq = *(const float2*)&s_zs[i][qb];
                float2 uq = *(const float2*)&s_us[i][qb];
                nh0 = fmaf(zq.x, wz, nh0); nh0 = fmaf(uq.x, wu, nh0);
                nh1 = fmaf(zq.y, wz, nh1); nh1 = fmaf(uq.y, wu, nh1);
            }
            float tw = s_termw[j], d1 = s_dnw[j], d2 = s_dnw[HID + j];
            float e1 = s_duw[j], e2 = s_duw[HID + j];
            float l0 = nh0 * tw, l1 = nh1 * tw;
            float qd0 = fmaf(nh0, d1, z0 * d2), qd1 = fmaf(nh1, d1, z1 * d2);
            float rd0 = fmaf(nh0, e1, z0 * e2), rd1 = fmaf(nh1, e1, z1 * e2);
            #pragma unroll
            for (int o = 16; o; o >>= 1) {
                l0  += __shfl_xor_sync(0xffffffffu, l0, o);
                l1  += __shfl_xor_sync(0xffffffffu, l1, o);
                qd0 += __shfl_xor_sync(0xffffffffu, qd0, o);
                qd1 += __shfl_xor_sync(0xffffffffu, qd1, o);
                rd0 += __shfl_xor_sync(0xffffffffu, rd0, o);
                rd1 += __shfl_xor_sync(0xffffffffu, rd1, o);
            }
            locmax = fmaxf(l0, l1) + __ldg(termb);
            float db = __ldg(dnb), du0 = __ldg(dub), dw64 = s_duw[64];
            float nn0 = qd0 + db, nn1 = qd1 + db;
            float ns0 = fmaf(nn0, dw64, rd0 + du0);
            float ns1 = fmaf(nn1, dw64, rd1 + du0);
            if (j < 2) {
                float nsv = (j == 0) ? ns0 : ns1;
                float nnv = (j == 0) ? nn0 : nn1;
                out[(t + 1) * N + n0 + j] = nsv;                  // preds
                out[T * N + T + (n0 + j) * (T - 1) + t] = nnv;    // preds_nextnode
            }
            if (!lastStep) {
                s_zs[j][qb + 0] = nh0; s_zs[j][qb + 1] = nh1;
                __syncwarp();
                const float2 p2 = *(const float2*)(pri + n0);
                float eb = __ldg(encb + j);
                float ew0 = s_encw[j], ew33 = s_encw[33 * HID + j];
                float zn0 = fmaf(ns0, ew0, fmaf(p2.x, ew33, eb));
                float zn1 = fmaf(ns1, ew0, fmaf(p2.y, ew33, eb));
                #pragma unroll
                for (int i = 0; i < HID; i++) {
                    float we = s_encw[(1 + i) * HID + j];
                    float2 hq = *(const float2*)&s_zs[i][qb];
                    zn0 = fmaf(hq.x, we, zn0); zn1 = fmaf(hq.y, we, zn1);
                }
                s_us[j][qb + 0] = zn0; s_us[j][qb + 1] = zn1;
                __syncwarp();
                float A0 = 0, A1 = 0, B0 = 0, B1 = 0;
                #pragma unroll
                for (int i = 0; i < HID; i++) {
                    float wa = s_Mw[i * HID + j], wb = s_Mw[(HID + i) * HID + j];
                    float2 zq = *(const float2*)&s_us[i][qb];
                    A0 = fmaf(zq.x, wa, A0); B0 = fmaf(zq.x, wb, B0);
                    A1 = fmaf(zq.y, wa, A1); B1 = fmaf(zq.y, wb, B1);
                }
                float mb = __ldg(Mb + j);
                float* __restrict__ Anew = g_A[(t & 1) ^ 1];
                int r = n0 * HID + j;
                Anew[r] = A0; Anew[r + HID] = A1;
                z0 = zn0; z1 = zn1;
                bc0 = B0 + mb; bc1 = B1 + mb;
            }
        }

        if (j == 0) s_red[w] = active ? locmax : -INFINITY;
        __syncthreads();
        if (tid == 0) {
            float m = -INFINITY;
            #pragma unroll
            for (int ww = 0; ww < 8; ww++) m = fmaxf(m, s_red[ww]);
            g_blockmax[t * 1024 + blockIdx.x] = m;
        }
        if (!lastStep) grid_sync_dev();
    }
}

// ---------------------------------------------------------------------------
// Finalize: preds_stop[0]=0, preds_stop[t+1]=sigmoid(max_blocks blockmax[t])
// ---------------------------------------------------------------------------
__global__ void k_final(float* __restrict__ out, int N, int T, int nblocks) {
    __shared__ float s_red[256];
    int t = blockIdx.x;
    float m = -INFINITY;
    for (int b = threadIdx.x; b < nblocks; b += blockDim.x)
        m = fmaxf(m, g_blockmax[t * 1024 + b]);
    s_red[threadIdx.x] = m;
    __syncthreads();
    for (int s = 128; s; s >>= 1) {
        if (threadIdx.x < s)
            s_red[threadIdx.x] = fmaxf(s_red[threadIdx.x], s_red[threadIdx.x + s]);
        __syncthreads();
    }
    if (threadIdx.x == 0) {
        float v = s_red[0];
        out[T * N + 1 + t] = 1.0f / (1.0f + expf(-v));
        if (t == 0) out[T * N] = 0.0f;
    }
}

// ---------------------------------------------------------------------------
extern "C" void kernel_launch(void* const* d_in, const int* in_sizes, int n_in,
                              void* d_out, int out_size) {
    const float* states   = (const float*)d_in[0];
    const float* priority = (const float*)d_in[1];
    const float* edges    = (const float*)d_in[2];
    const int*   src      = (const int*)d_in[3];
    const float* enc_w    = (const float*)d_in[5];
    const float* enc_b    = (const float*)d_in[6];
    const float* M_w      = (const float*)d_in[7];
    const float* M_b      = (const float*)d_in[8];
    const float* U_w      = (const float*)d_in[9];
    const float* U_b      = (const float*)d_in[10];
    const float* dn_w     = (const float*)d_in[11];
    const float* dn_b     = (const float*)d_in[12];
    const float* du_w     = (const float*)d_in[13];
    const float* du_b     = (const float*)d_in[14];
    const float* term_w   = (const float*)d_in[15];
    const float* term_b   = (const float*)d_in[16];
    float* out = (float*)d_out;

    int N = in_sizes[1];
    int E = in_sizes[3];
    int T = in_sizes[0] / N;
    int Kc = E / N;
    int Erem = E - Kc * N;
    int KS = Kc + (Erem ? 1 : 0);
    int KS8 = (KS + 7) & ~7;          // pad to multiple of 8

    int ptotal = N * KS8;
    k_prep<<<(ptotal + 255) / 256, 256>>>(edges, src, N, E, Kc, KS8, Erem);

    int nb = (N + 15) / 16;           // 625 for N=10000; all resident (<=740)
    k_all<<<nb, 256>>>(states, priority, enc_w, enc_b, M_w, M_b,
                       U_w, U_b, dn_w, dn_b, du_w, du_b,
                       term_w, term_b, out, N, T, KS8);

    k_final<<<T - 1, 256>>>(out, N, T, nb);
}

// round 13
// speedup vs baseline: 1.3639x; 1.0412x over previous
#include <cuda_runtime.h>
#include <math.h>

#define HID 32
#define MAXN 10240
#define MAXSEF 1100000

// device scratch (no allocs allowed)
__device__ __align__(16) float g_A[2][MAXN * HID];  // z @ M_w[0:32], dbl-buffered
__device__ __align__(16) int2 g_pair[MAXSEF];       // (src, ef bits) [n][k], padded
__device__ float g_blockmax[8 * 1024];
__device__ volatile unsigned g_gen;                 // barrier generation
__device__ unsigned g_cnt;                          // barrier arrival count

// ---------------------------------------------------------------------------
// Prologue: re-lay (src, edge_feat) into per-node int2 pairs, padded to KS8
// (multiple of 8) with duplicates of edge 0 (idempotent under max).
// dst[e] == e % N. edges_mat gather uses __ldcs: streaming, sector-granular,
// no 128B L2-line promotion, no L2 pollution.
// ---------------------------------------------------------------------------
__global__ void __launch_bounds__(256) k_prep(const float* __restrict__ edges,
                       const int* __restrict__ src,
                       int N, int E, int Kc, int KS8, int Erem, int total) {
    int o0 = (blockIdx.x * blockDim.x + threadIdx.x) * 4;
    #pragma unroll
    for (int v = 0; v < 4; v++) {
        int o = o0 + v;
        if (o >= total) return;
        int n = o / KS8, k = o - n * KS8;
        int kn = Kc + (n < Erem ? 1 : 0);
        int e = (k < kn) ? (k * N + n) : n;   // pad: duplicate edge k=0
        int s = __ldg(src + e);
        float f = __ldcs(edges + (long)s * N + n);
        g_pair[o] = make_int2(s, __float_as_int(f));
    }
}

// ---------------------------------------------------------------------------
// Software grid barrier (all blocks resident by construction).
// ---------------------------------------------------------------------------
__device__ __forceinline__ void grid_sync_dev() {
    __threadfence();
    __syncthreads();
    if (threadIdx.x == 0) {
        unsigned gen = g_gen;
        if (atomicAdd(&g_cnt, 1u) == gridDim.x - 1u) {
            g_cnt = 0u;
            __threadfence();
            g_gen = gen + 1u;
        } else {
            while (g_gen == gen) __nanosleep(32);
        }
    }
    __syncthreads();
}

// ---------------------------------------------------------------------------
// Persistent fused kernel: init + all T-1 steps. 8 warps, 2 nodes/warp,
// 16 nodes/block, grid ceil(N/16) (all blocks resident: launch_bounds(256,5)).
// z and Bc live in registers across steps; weights in smem loaded once.
// ---------------------------------------------------------------------------
__global__ void __launch_bounds__(256, 5) k_all(
        const float* __restrict__ states0, const float* __restrict__ pri,
        const float* __restrict__ encw, const float* __restrict__ encb,
        const float* __restrict__ Mw,   const float* __restrict__ Mb,
        const float* __restrict__ Uw,   const float* __restrict__ Ub,
        const float* __restrict__ dnw,  const float* __restrict__ dnb,
        const float* __restrict__ duw,  const float* __restrict__ dub,
        const float* __restrict__ termw,const float* __restrict__ termb,
        float* __restrict__ out, int N, int T, int KS8) {
    __shared__ float s_encw[34 * HID];
    __shared__ float s_Uw[64 * HID];
    __shared__ float s_Mw[64 * HID];
    __shared__ float s_dnw[64];
    __shared__ float s_duw[65];
    __shared__ float s_termw[HID];
    __shared__ __align__(16) float s_um[8][64];
    __shared__ __align__(8) float s_zs[HID][18];
    __shared__ __align__(8) float s_us[HID][18];
    __shared__ float s_red[8];

    int tid = threadIdx.x;
    for (int i = tid; i < 34 * HID; i += 256) s_encw[i] = encw[i];
    for (int i = tid; i < 64 * HID; i += 256) s_Mw[i] = Mw[i];
    for (int i = tid; i < 64 * HID; i += 256) s_Uw[i] = Uw[i];
    if (tid < 64) s_dnw[tid] = dnw[tid];
    if (tid < 65) s_duw[tid] = duw[tid];
    if (tid < HID) s_termw[tid] = termw[tid];
    __syncthreads();

    int w = tid >> 5, j = tid & 31, qb = w * 2;
    int n0 = blockIdx.x * 16 + qb;
    bool active = (n0 < N);
    int g = j >> 3, c4 = (j & 7) << 2;      // lane group, col base
    const float4 fw4 = *(const float4*)(Mw + 64 * HID + c4);

    float z0 = 0.f, z1 = 0.f, bc0 = 0.f, bc1 = 0.f;

    // ---------------- init: z0/A0/Bc0 from states[0], preds[0] --------------
    if (active) {
        const float2 st2 = *(const float2*)(states0 + n0);
        const float2 p2  = *(const float2*)(pri + n0);
        float eb = __ldg(encb + j);
        float ew0 = s_encw[j], ew33 = s_encw[33 * HID + j];
        z0 = fmaf(st2.x, ew0, fmaf(p2.x, ew33, eb));
        z1 = fmaf(st2.y, ew0, fmaf(p2.y, ew33, eb));
        if (j < 2) out[n0 + j] = (j == 0) ? st2.x : st2.y;
        s_zs[j][qb + 0] = z0; s_zs[j][qb + 1] = z1;
        __syncwarp();
        float A0 = 0, A1 = 0, B0 = 0, B1 = 0;
        #pragma unroll
        for (int i = 0; i < HID; i++) {
            float wa = s_Mw[i * HID + j], wb = s_Mw[(HID + i) * HID + j];
            float2 zq = *(const float2*)&s_zs[i][qb];
            A0 = fmaf(zq.x, wa, A0); B0 = fmaf(zq.x, wb, B0);
            A1 = fmaf(zq.y, wa, A1); B1 = fmaf(zq.y, wb, B1);
        }
        float mb = __ldg(Mb + j);
        int r = n0 * HID + j;
        g_A[0][r] = A0; g_A[0][r + HID] = A1;
        bc0 = B0 + mb; bc1 = B1 + mb;
    }
    grid_sync_dev();

    // ---------------- T-1 fused steps ---------------------------------------
    for (int t = 0; t < T - 1; t++) {
        bool lastStep = (t == T - 2);
        float locmax = -INFINITY;

        if (active) {
            const float* __restrict__ Aold = g_A[t & 1];
            #pragma unroll
            for (int qi = 0; qi < 2; qi++) {
                const int2* __restrict__ pp = g_pair + (long)(n0 + qi) * KS8 + g;
                float mx = -INFINITY, my = -INFINITY, mz = -INFINITY, mw2 = -INFINITY;
                for (int k = 0; k < KS8; k += 8) {
                    int2 q0 = __ldg(pp + k);
                    int2 q1 = __ldg(pp + k + 4);
                    float4 a0 = __ldg((const float4*)(Aold + (q0.x << 5) + c4));
                    float4 a1 = __ldg((const float4*)(Aold + (q1.x << 5) + c4));
                    float f0 = __int_as_float(q0.y);
                    float f1 = __int_as_float(q1.y);
                    mx  = fmaxf(mx,  fmaf(f0, fw4.x, a0.x));
                    my  = fmaxf(my,  fmaf(f0, fw4.y, a0.y));
                    mz  = fmaxf(mz,  fmaf(f0, fw4.z, a0.z));
                    mw2 = fmaxf(mw2, fmaf(f0, fw4.w, a0.w));
                    mx  = fmaxf(mx,  fmaf(f1, fw4.x, a1.x));
                    my  = fmaxf(my,  fmaf(f1, fw4.y, a1.y));
                    mz  = fmaxf(mz,  fmaf(f1, fw4.z, a1.z));
                    mw2 = fmaxf(mw2, fmaf(f1, fw4.w, a1.w));
                }
                mx  = fmaxf(mx,  __shfl_xor_sync(0xffffffffu, mx, 8));
                my  = fmaxf(my,  __shfl_xor_sync(0xffffffffu, my, 8));
                mz  = fmaxf(mz,  __shfl_xor_sync(0xffffffffu, mz, 8));
                mw2 = fmaxf(mw2, __shfl_xor_sync(0xffffffffu, mw2, 8));
                mx  = fmaxf(mx,  __shfl_xor_sync(0xffffffffu, mx, 16));
                my  = fmaxf(my,  __shfl_xor_sync(0xffffffffu, my, 16));
                mz  = fmaxf(mz,  __shfl_xor_sync(0xffffffffu, mz, 16));
                mw2 = fmaxf(mw2, __shfl_xor_sync(0xffffffffu, mw2, 16));
                if (g == 0)
                    *(float4*)&s_um[w][qi * 32 + c4] = make_float4(mx, my, mz, mw2);
            }
            __syncwarp();

            // ---------------- node phase (z, Bc in registers) ---------------
            float u0 = bc0 + s_um[w][j];
            float u1 = bc1 + s_um[w][32 + j];
            s_zs[j][qb + 0] = z0; s_zs[j][qb + 1] = z1;
            s_us[j][qb + 0] = u0; s_us[j][qb + 1] = u1;
            __syncwarp();
            float ub = __ldg(Ub + j);
            float nh0 = ub, nh1 = ub;
            #pragma unroll
            for (int i = 0; i < HID; i++) {
                float wz = s_Uw[i * HID + j], wu = s_Uw[(HID + i) * HID + j];
                float2 zq = *(const float2*)&s_zs[i][qb];
                float2 uq = *(const float2*)&s_us[i][qb];
                nh0 = fmaf(zq.x, wz, nh0); nh0 = fmaf(uq.x, wu, nh0);
                nh1 = fmaf(zq.y, wz, nh1); nh1 = fmaf(uq.y, wu, nh1);
            }
            float tw = s_termw[j], d1 = s_dnw[j], d2 = s_dnw[HID + j];
            float e1 = s_duw[j], e2 = s_duw[HID + j];
            float l0 = nh0 * tw, l1 = nh1 * tw;
            float qd0 = fmaf(nh0, d1, z0 * d2), qd1 = fmaf(nh1, d1, z1 * d2);
            float rd0 = fmaf(nh0, e1, z0 * e2), rd1 = fmaf(nh1, e1, z1 * e2);
            #pragma unroll
            for (int o = 16; o; o >>= 1) {
                l0  += __shfl_xor_sync(0xffffffffu, l0, o);
                l1  += __shfl_xor_sync(0xffffffffu, l1, o);
                qd0 += __shfl_xor_sync(0xffffffffu, qd0, o);
                qd1 += __shfl_xor_sync(0xffffffffu, qd1, o);
                rd0 += __shfl_xor_sync(0xffffffffu, rd0, o);
                rd1 += __shfl_xor_sync(0xffffffffu, rd1, o);
            }
            locmax = fmaxf(l0, l1) + __ldg(termb);
            float db = __ldg(dnb), du0 = __ldg(dub), dw64 = s_duw[64];
            float nn0 = qd0 + db, nn1 = qd1 + db;
            float ns0 = fmaf(nn0, dw64, rd0 + du0);
            float ns1 = fmaf(nn1, dw64, rd1 + du0);
            if (j < 2) {
                float nsv = (j == 0) ? ns0 : ns1;
                float nnv = (j == 0) ? nn0 : nn1;
                out[(t + 1) * N + n0 + j] = nsv;                  // preds
                out[T * N + T + (n0 + j) * (T - 1) + t] = nnv;    // preds_nextnode
            }
            if (!lastStep) {
                s_zs[j][qb + 0] = nh0; s_zs[j][qb + 1] = nh1;
                __syncwarp();
                const float2 p2 = *(const float2*)(pri + n0);
                float eb = __ldg(encb + j);
                float ew0 = s_encw[j], ew33 = s_encw[33 * HID + j];
                float zn0 = fmaf(ns0, ew0, fmaf(p2.x, ew33, eb));
                float zn1 = fmaf(ns1, ew0, fmaf(p2.y, ew33, eb));
                #pragma unroll
                for (int i = 0; i < HID; i++) {
                    float we = s_encw[(1 + i) * HID + j];
                    float2 hq = *(const float2*)&s_zs[i][qb];
                    zn0 = fmaf(hq.x, we, zn0); zn1 = fmaf(hq.y, we, zn1);
                }
                s_us[j][qb + 0] = zn0; s_us[j][qb + 1] = zn1;
                __syncwarp();
                float A0 = 0, A1 = 0, B0 = 0, B1 = 0;
                #pragma unroll
                for (int i = 0; i < HID; i++) {
                    float wa = s_Mw[i * HID + j], wb = s_Mw[(HID + i) * HID + j];
                    float2 zq = *(const float2*)&s_us[i][qb];
                    A0 = fmaf(zq.x, wa, A0); B0 = fmaf(zq.x, wb, B0);
                    A1 = fmaf(zq.y, wa, A1); B1 = fmaf(zq.y, wb, B1);
                }
                float mb = __ldg(Mb + j);
                float* __restrict__ Anew = g_A[(t & 1) ^ 1];
                int r = n0 * HID + j;
                Anew[r] = A0; Anew[r + HID] = A1;
                z0 = zn0; z1 = zn1;
                bc0 = B0 + mb; bc1 = B1 + mb;
            }
        }

        if (j == 0) s_red[w] = active ? locmax : -INFINITY;
        __syncthreads();
        if (tid == 0) {
            float m = -INFINITY;
            #pragma unroll
            for (int ww = 0; ww < 8; ww++) m = fmaxf(m, s_red[ww]);
            g_blockmax[t * 1024 + blockIdx.x] = m;
        }
        if (!lastStep) grid_sync_dev();
    }
}

// ---------------------------------------------------------------------------
// Finalize: preds_stop[0]=0, preds_stop[t+1]=sigmoid(max_blocks blockmax[t])
// ---------------------------------------------------------------------------
__global__ void k_final(float* __restrict__ out, int N, int T, int nblocks) {
    __shared__ float s_red[256];
    int t = blockIdx.x;
    float m = -INFINITY;
    for (int b = threadIdx.x; b < nblocks; b += blockDim.x)
        m = fmaxf(m, g_blockmax[t * 1024 + b]);
    s_red[threadIdx.x] = m;
    __syncthreads();
    for (int s = 128; s; s >>= 1) {
        if (threadIdx.x < s)
            s_red[threadIdx.x] = fmaxf(s_red[threadIdx.x], s_red[threadIdx.x + s]);
        __syncthreads();
    }
    if (threadIdx.x == 0) {
        float v = s_red[0];
        out[T * N + 1 + t] = 1.0f / (1.0f + expf(-v));
        if (t == 0) out[T * N] = 0.0f;
    }
}

// ---------------------------------------------------------------------------
extern "C" void kernel_launch(void* const* d_in, const int* in_sizes, int n_in,
                              void* d_out, int out_size) {
    const float* states   = (const float*)d_in[0];
    const float* priority = (const float*)d_in[1];
    const float* edges    = (const float*)d_in[2];
    const int*   src      = (const int*)d_in[3];
    const float* enc_w    = (const float*)d_in[5];
    const float* enc_b    = (const float*)d_in[6];
    const float* M_w      = (const float*)d_in[7];
    const float* M_b      = (const float*)d_in[8];
    const float* U_w      = (const float*)d_in[9];
    const float* U_b      = (const float*)d_in[10];
    const float* dn_w     = (const float*)d_in[11];
    const float* dn_b     = (const float*)d_in[12];
    const float* du_w     = (const float*)d_in[13];
    const float* du_b     = (const float*)d_in[14];
    const float* term_w   = (const float*)d_in[15];
    const float* term_b   = (const float*)d_in[16];
    float* out = (float*)d_out;

    int N = in_sizes[1];
    int E = in_sizes[3];
    int T = in_sizes[0] / N;
    int Kc = E / N;
    int Erem = E - Kc * N;
    int KS = Kc + (Erem ? 1 : 0);
    int KS8 = (KS + 7) & ~7;          // pad to multiple of 8

    int ptotal = N * KS8;
    int pthreads = (ptotal + 3) / 4;
    k_prep<<<(pthreads + 255) / 256, 256>>>(edges, src, N, E, Kc, KS8, Erem, ptotal);

    int nb = (N + 15) / 16;           // 625 for N=10000; all resident (<=740)
    k_all<<<nb, 256>>>(states, priority, enc_w, enc_b, M_w, M_b,
                       U_w, U_b, dn_w, dn_b, du_w, du_b,
                       term_w, term_b, out, N, T, KS8);

    k_final<<<T - 1, 256>>>(out, N, T, nb);
}

// round 14
// speedup vs baseline: 1.3959x; 1.0234x over previous
#include <cuda_runtime.h>
#include <math.h>

#define HID 32
#define MAXN 10240
#define MAXSEF 1100000

// device scratch (no allocs allowed)
__device__ __align__(16) float g_A[2][MAXN * HID];  // z @ M_w[0:32], dbl-buffered
__device__ __align__(16) int2 g_pair[MAXSEF];       // (src, ef bits) [n][k], padded
__device__ float g_blockmax[8 * 1024];
__device__ volatile unsigned g_gen;                 // barrier generation
__device__ unsigned g_cnt;                          // barrier arrival count

// ---------------------------------------------------------------------------
// Software grid barrier (all blocks resident by construction).
// ---------------------------------------------------------------------------
__device__ __forceinline__ void grid_sync_dev() {
    __threadfence();
    __syncthreads();
    if (threadIdx.x == 0) {
        unsigned gen = g_gen;
        if (atomicAdd(&g_cnt, 1u) == gridDim.x - 1u) {
            g_cnt = 0u;
            __threadfence();
            g_gen = gen + 1u;
        } else {
            while (g_gen == gen) __nanosleep(32);
        }
    }
    __syncthreads();
}

// ---------------------------------------------------------------------------
// Persistent fused kernel: init + all T-1 steps. 8 warps, 2 nodes/warp,
// 16 nodes/block, grid ceil(N/16) (all blocks resident: launch_bounds(256,5)).
// Step 0 gathers edge features from edges_mat on the fly (DRAM random reads
// overlapped with the L2 A-row gathers) and caches (src, ef) into g_pair for
// steps 1..T-2. z and Bc live in registers across steps.
// ---------------------------------------------------------------------------
__global__ void __launch_bounds__(256, 5) k_all(
        const float* __restrict__ states0, const float* __restrict__ pri,
        const float* __restrict__ edges,  const int* __restrict__ src,
        const float* __restrict__ encw, const float* __restrict__ encb,
        const float* __restrict__ Mw,   const float* __restrict__ Mb,
        const float* __restrict__ Uw,   const float* __restrict__ Ub,
        const float* __restrict__ dnw,  const float* __restrict__ dnb,
        const float* __restrict__ duw,  const float* __restrict__ dub,
        const float* __restrict__ termw,const float* __restrict__ termb,
        float* __restrict__ out, int N, int T, int KS8, int Kc, int Erem) {
    __shared__ float s_encw[34 * HID];
    __shared__ float s_Uw[64 * HID];
    __shared__ float s_Mw[64 * HID];
    __shared__ float s_dnw[64];
    __shared__ float s_duw[65];
    __shared__ float s_termw[HID];
    __shared__ __align__(16) float s_um[8][64];
    __shared__ __align__(8) float s_zs[HID][18];
    __shared__ __align__(8) float s_us[HID][18];
    __shared__ float s_red[8];

    int tid = threadIdx.x;
    for (int i = tid; i < 34 * HID; i += 256) s_encw[i] = encw[i];
    for (int i = tid; i < 64 * HID; i += 256) s_Mw[i] = Mw[i];
    for (int i = tid; i < 64 * HID; i += 256) s_Uw[i] = Uw[i];
    if (tid < 64) s_dnw[tid] = dnw[tid];
    if (tid < 65) s_duw[tid] = duw[tid];
    if (tid < HID) s_termw[tid] = termw[tid];
    __syncthreads();

    int w = tid >> 5, j = tid & 31, qb = w * 2;
    int n0 = blockIdx.x * 16 + qb;
    bool active = (n0 < N);
    int g = j >> 3, c4 = (j & 7) << 2;      // lane group, col base
    bool gl = ((j & 7) == 0);               // group leader lane
    const float4 fw4 = *(const float4*)(Mw + 64 * HID + c4);

    float z0 = 0.f, z1 = 0.f, bc0 = 0.f, bc1 = 0.f;

    // ---------------- init: z0/A0/Bc0 from states[0], preds[0] --------------
    if (active) {
        const float2 st2 = *(const float2*)(states0 + n0);
        const float2 p2  = *(const float2*)(pri + n0);
        float eb = __ldg(encb + j);
        float ew0 = s_encw[j], ew33 = s_encw[33 * HID + j];
        z0 = fmaf(st2.x, ew0, fmaf(p2.x, ew33, eb));
        z1 = fmaf(st2.y, ew0, fmaf(p2.y, ew33, eb));
        if (j < 2) out[n0 + j] = (j == 0) ? st2.x : st2.y;
        s_zs[j][qb + 0] = z0; s_zs[j][qb + 1] = z1;
        __syncwarp();
        float A0 = 0, A1 = 0, B0 = 0, B1 = 0;
        #pragma unroll
        for (int i = 0; i < HID; i++) {
            float wa = s_Mw[i * HID + j], wb = s_Mw[(HID + i) * HID + j];
            float2 zq = *(const float2*)&s_zs[i][qb];
            A0 = fmaf(zq.x, wa, A0); B0 = fmaf(zq.x, wb, B0);
            A1 = fmaf(zq.y, wa, A1); B1 = fmaf(zq.y, wb, B1);
        }
        float mb = __ldg(Mb + j);
        int r = n0 * HID + j;
        g_A[0][r] = A0; g_A[0][r + HID] = A1;
        bc0 = B0 + mb; bc1 = B1 + mb;
    }
    grid_sync_dev();

    // ---------------- T-1 fused steps ---------------------------------------
    for (int t = 0; t < T - 1; t++) {
        bool lastStep = (t == T - 2);
        float locmax = -INFINITY;

        if (active) {
            const float* __restrict__ Aold = g_A[t & 1];
            #pragma unroll
            for (int qi = 0; qi < 2; qi++) {
                int n = n0 + qi;
                float mx = -INFINITY, my = -INFINITY, mz = -INFINITY, mw2 = -INFINITY;
                if (t == 0) {
                    // fused ef gather: src from L2, edges from DRAM (random),
                    // cache (s, ef) into g_pair for later steps.
                    int kn = Kc + (n < Erem ? 1 : 0);
                    long base = (long)n * KS8;
                    for (int k = 0; k < KS8; k += 8) {
                        int k0 = k + g, k1 = k + 4 + g;
                        int e0 = (k0 < kn) ? k0 * N + n : n;
                        int e1 = (k1 < kn) ? k1 * N + n : n;
                        int s0 = __ldg(src + e0);
                        int s1 = __ldg(src + e1);
                        float f0 = __ldcs(edges + (long)s0 * N + n);
                        float f1 = __ldcs(edges + (long)s1 * N + n);
                        if (gl) {
                            g_pair[base + k0] = make_int2(s0, __float_as_int(f0));
                            g_pair[base + k1] = make_int2(s1, __float_as_int(f1));
                        }
                        float4 a0 = __ldg((const float4*)(Aold + (s0 << 5) + c4));
                        float4 a1 = __ldg((const float4*)(Aold + (s1 << 5) + c4));
                        mx  = fmaxf(mx,  fmaf(f0, fw4.x, a0.x));
                        my  = fmaxf(my,  fmaf(f0, fw4.y, a0.y));
                        mz  = fmaxf(mz,  fmaf(f0, fw4.z, a0.z));
                        mw2 = fmaxf(mw2, fmaf(f0, fw4.w, a0.w));
                        mx  = fmaxf(mx,  fmaf(f1, fw4.x, a1.x));
                        my  = fmaxf(my,  fmaf(f1, fw4.y, a1.y));
                        mz  = fmaxf(mz,  fmaf(f1, fw4.z, a1.z));
                        mw2 = fmaxf(mw2, fmaf(f1, fw4.w, a1.w));
                    }
                } else {
                    const int2* __restrict__ pp = g_pair + (long)n * KS8 + g;
                    for (int k = 0; k < KS8; k += 8) {
                        int2 q0 = __ldg(pp + k);
                        int2 q1 = __ldg(pp + k + 4);
                        float4 a0 = __ldg((const float4*)(Aold + (q0.x << 5) + c4));
                        float4 a1 = __ldg((const float4*)(Aold + (q1.x << 5) + c4));
                        float f0 = __int_as_float(q0.y);
                        float f1 = __int_as_float(q1.y);
                        mx  = fmaxf(mx,  fmaf(f0, fw4.x, a0.x));
                        my  = fmaxf(my,  fmaf(f0, fw4.y, a0.y));
                        mz  = fmaxf(mz,  fmaf(f0, fw4.z, a0.z));
                        mw2 = fmaxf(mw2, fmaf(f0, fw4.w, a0.w));
                        mx  = fmaxf(mx,  fmaf(f1, fw4.x, a1.x));
                        my  = fmaxf(my,  fmaf(f1, fw4.y, a1.y));
                        mz  = fmaxf(mz,  fmaf(f1, fw4.z, a1.z));
                        mw2 = fmaxf(mw2, fmaf(f1, fw4.w, a1.w));
                    }
                }
                mx  = fmaxf(mx,  __shfl_xor_sync(0xffffffffu, mx, 8));
                my  = fmaxf(my,  __shfl_xor_sync(0xffffffffu, my, 8));
                mz  = fmaxf(mz,  __shfl_xor_sync(0xffffffffu, mz, 8));
                mw2 = fmaxf(mw2, __shfl_xor_sync(0xffffffffu, mw2, 8));
                mx  = fmaxf(mx,  __shfl_xor_sync(0xffffffffu, mx, 16));
                my  = fmaxf(my,  __shfl_xor_sync(0xffffffffu, my, 16));
                mz  = fmaxf(mz,  __shfl_xor_sync(0xffffffffu, mz, 16));
                mw2 = fmaxf(mw2, __shfl_xor_sync(0xffffffffu, mw2, 16));
                if (g == 0)
                    *(float4*)&s_um[w][qi * 32 + c4] = make_float4(mx, my, mz, mw2);
            }
            __syncwarp();

            // ---------------- node phase (z, Bc in registers) ---------------
            float u0 = bc0 + s_um[w][j];
            float u1 = bc1 + s_um[w][32 + j];
            s_zs[j][qb + 0] = z0; s_zs[j][qb + 1] = z1;
            s_us[j][qb + 0] = u0; s_us[j][qb + 1] = u1;
            __syncwarp();
            float ub = __ldg(Ub + j);
            float nh0 = ub, nh1 = ub;
            #pragma unroll
            for (int i = 0; i < HID; i++) {
                float wz = s_Uw[i * HID + j], wu = s_Uw[(HID + i) * HID + j];
                float2 zq = *(const float2*)&s_zs[i][qb];
                float2 uq = *(const float2*)&s_us[i][qb];
                nh0 = fmaf(zq.x, wz, nh0); nh0 = fmaf(uq.x, wu, nh0);
                nh1 = fmaf(zq.y, wz, nh1); nh1 = fmaf(uq.y, wu, nh1);
            }
            float tw = s_termw[j], d1 = s_dnw[j], d2 = s_dnw[HID + j];
            float e1 = s_duw[j], e2 = s_duw[HID + j];
            float l0 = nh0 * tw, l1 = nh1 * tw;
            float qd0 = fmaf(nh0, d1, z0 * d2), qd1 = fmaf(nh1, d1, z1 * d2);
            float rd0 = fmaf(nh0, e1, z0 * e2), rd1 = fmaf(nh1, e1, z1 * e2);
            #pragma unroll
            for (int o = 16; o; o >>= 1) {
                l0  += __shfl_xor_sync(0xffffffffu, l0, o);
                l1  += __shfl_xor_sync(0xffffffffu, l1, o);
                qd0 += __shfl_xor_sync(0xffffffffu, qd0, o);
                qd1 += __shfl_xor_sync(0xffffffffu, qd1, o);
                rd0 += __shfl_xor_sync(0xffffffffu, rd0, o);
                rd1 += __shfl_xor_sync(0xffffffffu, rd1, o);
            }
            locmax = fmaxf(l0, l1) + __ldg(termb);
            float db = __ldg(dnb), du0 = __ldg(dub), dw64 = s_duw[64];
            float nn0 = qd0 + db, nn1 = qd1 + db;
            float ns0 = fmaf(nn0, dw64, rd0 + du0);
            float ns1 = fmaf(nn1, dw64, rd1 + du0);
            if (j < 2) {
                float nsv = (j == 0) ? ns0 : ns1;
                float nnv = (j == 0) ? nn0 : nn1;
                out[(t + 1) * N + n0 + j] = nsv;                  // preds
                out[T * N + T + (n0 + j) * (T - 1) + t] = nnv;    // preds_nextnode
            }
            if (!lastStep) {
                s_zs[j][qb + 0] = nh0; s_zs[j][qb + 1] = nh1;
                __syncwarp();
                const float2 p2 = *(const float2*)(pri + n0);
                float eb = __ldg(encb + j);
                float ew0 = s_encw[j], ew33 = s_encw[33 * HID + j];
                float zn0 = fmaf(ns0, ew0, fmaf(p2.x, ew33, eb));
                float zn1 = fmaf(ns1, ew0, fmaf(p2.y, ew33, eb));
                #pragma unroll
                for (int i = 0; i < HID; i++) {
                    float we = s_encw[(1 + i) * HID + j];
                    float2 hq = *(const float2*)&s_zs[i][qb];
                    zn0 = fmaf(hq.x, we, zn0); zn1 = fmaf(hq.y, we, zn1);
                }
                s_us[j][qb + 0] = zn0; s_us[j][qb + 1] = zn1;
                __syncwarp();
                float A0 = 0, A1 = 0, B0 = 0, B1 = 0;
                #pragma unroll
                for (int i = 0; i < HID; i++) {
                    float wa = s_Mw[i * HID + j], wb = s_Mw[(HID + i) * HID + j];
                    float2 zq = *(const float2*)&s_us[i][qb];
                    A0 = fmaf(zq.x, wa, A0); B0 = fmaf(zq.x, wb, B0);
                    A1 = fmaf(zq.y, wa, A1); B1 = fmaf(zq.y, wb, B1);
                }
                float mb = __ldg(Mb + j);
                float* __restrict__ Anew = g_A[(t & 1) ^ 1];
                int r = n0 * HID + j;
                Anew[r] = A0; Anew[r + HID] = A1;
                z0 = zn0; z1 = zn1;
                bc0 = B0 + mb; bc1 = B1 + mb;
            }
        }

        if (j == 0) s_red[w] = active ? locmax : -INFINITY;
        __syncthreads();
        if (tid == 0) {
            float m = -INFINITY;
            #pragma unroll
            for (int ww = 0; ww < 8; ww++) m = fmaxf(m, s_red[ww]);
            g_blockmax[t * 1024 + blockIdx.x] = m;
        }
        if (!lastStep) grid_sync_dev();
    }
}

// ---------------------------------------------------------------------------
// Finalize: preds_stop[0]=0, preds_stop[t+1]=sigmoid(max_blocks blockmax[t])
// ---------------------------------------------------------------------------
__global__ void k_final(float* __restrict__ out, int N, int T, int nblocks) {
    __shared__ float s_red[256];
    int t = blockIdx.x;
    float m = -INFINITY;
    for (int b = threadIdx.x; b < nblocks; b += blockDim.x)
        m = fmaxf(m, g_blockmax[t * 1024 + b]);
    s_red[threadIdx.x] = m;
    __syncthreads();
    for (int s = 128; s; s >>= 1) {
        if (threadIdx.x < s)
            s_red[threadIdx.x] = fmaxf(s_red[threadIdx.x], s_red[threadIdx.x + s]);
        __syncthreads();
    }
    if (threadIdx.x == 0) {
        float v = s_red[0];
        out[T * N + 1 + t] = 1.0f / (1.0f + expf(-v));
        if (t == 0) out[T * N] = 0.0f;
    }
}

// ---------------------------------------------------------------------------
extern "C" void kernel_launch(void* const* d_in, const int* in_sizes, int n_in,
                              void* d_out, int out_size) {
    const float* states   = (const float*)d_in[0];
    const float* priority = (const float*)d_in[1];
    const float* edges    = (const float*)d_in[2];
    const int*   src      = (const int*)d_in[3];
    const float* enc_w    = (const float*)d_in[5];
    const float* enc_b    = (const float*)d_in[6];
    const float* M_w      = (const float*)d_in[7];
    const float* M_b      = (const float*)d_in[8];
    const float* U_w      = (const float*)d_in[9];
    const float* U_b      = (const float*)d_in[10];
    const float* dn_w     = (const float*)d_in[11];
    const float* dn_b     = (const float*)d_in[12];
    const float* du_w     = (const float*)d_in[13];
    const float* du_b     = (const float*)d_in[14];
    const float* term_w   = (const float*)d_in[15];
    const float* term_b   = (const float*)d_in[16];
    float* out = (float*)d_out;

    int N = in_sizes[1];
    int E = in_sizes[3];
    int T = in_sizes[0] / N;
    int Kc = E / N;
    int Erem = E - Kc * N;
    int KS = Kc + (Erem ? 1 : 0);
    int KS8 = (KS + 7) & ~7;          // pad to multiple of 8

    int nb = (N + 15) / 16;           // 625 for N=10000; all resident (<=740)
    k_all<<<nb, 256>>>(states, priority, edges, src, enc_w, enc_b, M_w, M_b,
                       U_w, U_b, dn_w, dn_b, du_w, du_b,
                       term_w, term_b, out, N, T, KS8, Kc, Erem);

    k_final<<<T - 1, 256>>>(out, N, T, nb);
}

// round 15
// speedup vs baseline: 1.3977x; 1.0013x over previous
#include <cuda_runtime.h>
#include <math.h>

#define HID 32
#define MAXN 10240
#define MAXSEF 1100000

// device scratch (no allocs allowed)
__device__ __align__(16) float g_A[2][MAXN * HID];  // z @ M_w[0:32], dbl-buffered
__device__ __align__(16) int2 g_pair[MAXSEF];       // (src, ef bits) [n][k], padded
__device__ float g_blockmax[8 * 1024];
__device__ volatile unsigned g_gen;                 // barrier generation
__device__ unsigned g_cnt;                          // barrier arrival count

// ---------------------------------------------------------------------------
// Software grid barrier (all blocks resident by construction).
// ---------------------------------------------------------------------------
__device__ __forceinline__ void grid_sync_dev() {
    __threadfence();
    __syncthreads();
    if (threadIdx.x == 0) {
        unsigned gen = g_gen;
        if (atomicAdd(&g_cnt, 1u) == gridDim.x - 1u) {
            g_cnt = 0u;
            __threadfence();
            g_gen = gen + 1u;
        } else {
            while (g_gen == gen) __nanosleep(32);
        }
    }
    __syncthreads();
}

// ---------------------------------------------------------------------------
// Persistent fused kernel: init + all T-1 steps + finalize. 8 warps,
// 2 nodes/warp, 16 nodes/block, grid ceil(N/16) (all resident: lb(256,5)).
// Step 0 gathers edge features from edges_mat on the fly and caches (src, ef)
// into g_pair for steps >=1. z and Bc live in registers across steps.
// ---------------------------------------------------------------------------
__global__ void __launch_bounds__(256, 5) k_all(
        const float* __restrict__ states0, const float* __restrict__ pri,
        const float* __restrict__ edges,  const int* __restrict__ src,
        const float* __restrict__ encw, const float* __restrict__ encb,
        const float* __restrict__ Mw,   const float* __restrict__ Mb,
        const float* __restrict__ Uw,   const float* __restrict__ Ub,
        const float* __restrict__ dnw,  const float* __restrict__ dnb,
        const float* __restrict__ duw,  const float* __restrict__ dub,
        const float* __restrict__ termw,const float* __restrict__ termb,
        float* __restrict__ out, int N, int T, int KS8, int Kc, int Erem) {
    __shared__ float s_encw[34 * HID];
    __shared__ float s_Uw[64 * HID];
    __shared__ float s_Mw[64 * HID];
    __shared__ float s_dnw[64];
    __shared__ float s_duw[65];
    __shared__ float s_termw[HID];
    __shared__ __align__(16) float s_um[8][64];
    __shared__ __align__(8) float s_zs[HID][18];
    __shared__ __align__(8) float s_us[HID][18];
    __shared__ float s_red[8];
    __shared__ float s_fin[256];

    int tid = threadIdx.x;
    for (int i = tid; i < 34 * HID; i += 256) s_encw[i] = encw[i];
    for (int i = tid; i < 64 * HID; i += 256) s_Mw[i] = Mw[i];
    for (int i = tid; i < 64 * HID; i += 256) s_Uw[i] = Uw[i];
    if (tid < 64) s_dnw[tid] = dnw[tid];
    if (tid < 65) s_duw[tid] = duw[tid];
    if (tid < HID) s_termw[tid] = termw[tid];
    __syncthreads();

    int w = tid >> 5, j = tid & 31, qb = w * 2;
    int n0 = blockIdx.x * 16 + qb;
    bool active = (n0 < N);
    int g = j >> 3, c4 = (j & 7) << 2;      // lane group, col base
    bool gl = ((j & 7) == 0);               // group leader lane
    const float4 fw4 = *(const float4*)(Mw + 64 * HID + c4);

    float z0 = 0.f, z1 = 0.f, bc0 = 0.f, bc1 = 0.f;

    // ---------------- init: z0/A0/Bc0 from states[0], preds[0] --------------
    if (active) {
        const float2 st2 = *(const float2*)(states0 + n0);
        const float2 p2  = *(const float2*)(pri + n0);
        float eb = __ldg(encb + j);
        float ew0 = s_encw[j], ew33 = s_encw[33 * HID + j];
        z0 = fmaf(st2.x, ew0, fmaf(p2.x, ew33, eb));
        z1 = fmaf(st2.y, ew0, fmaf(p2.y, ew33, eb));
        if (j < 2) out[n0 + j] = (j == 0) ? st2.x : st2.y;
        s_zs[j][qb + 0] = z0; s_zs[j][qb + 1] = z1;
        __syncwarp();
        float A0 = 0, A1 = 0, B0 = 0, B1 = 0;
        #pragma unroll
        for (int i = 0; i < HID; i++) {
            float wa = s_Mw[i * HID + j], wb = s_Mw[(HID + i) * HID + j];
            float2 zq = *(const float2*)&s_zs[i][qb];
            A0 = fmaf(zq.x, wa, A0); B0 = fmaf(zq.x, wb, B0);
            A1 = fmaf(zq.y, wa, A1); B1 = fmaf(zq.y, wb, B1);
        }
        float mb = __ldg(Mb + j);
        int r = n0 * HID + j;
        g_A[0][r] = A0; g_A[0][r + HID] = A1;
        bc0 = B0 + mb; bc1 = B1 + mb;
    }
    grid_sync_dev();

    // ---------------- T-1 fused steps ---------------------------------------
    for (int t = 0; t < T - 1; t++) {
        bool lastStep = (t == T - 2);
        float locmax = -INFINITY;

        if (active) {
            const float* __restrict__ Aold = g_A[t & 1];
            #pragma unroll
            for (int qi = 0; qi < 2; qi++) {
                int n = n0 + qi;
                float mx = -INFINITY, my = -INFINITY, mz = -INFINITY, mw2 = -INFINITY;
                if (t == 0) {
                    // fused ef gather: src from L2, edges from DRAM (random),
                    // cache (s, ef) into g_pair for later steps.
                    int kn = Kc + (n < Erem ? 1 : 0);
                    long base = (long)n * KS8;
                    for (int k = 0; k < KS8; k += 8) {
                        int k0 = k + g, k1 = k + 4 + g;
                        int e0 = (k0 < kn) ? k0 * N + n : n;
                        int e1 = (k1 < kn) ? k1 * N + n : n;
                        int s0 = __ldg(src + e0);
                        int s1 = __ldg(src + e1);
                        float f0 = __ldcs(edges + (long)s0 * N + n);
                        float f1 = __ldcs(edges + (long)s1 * N + n);
                        if (gl) {
                            g_pair[base + k0] = make_int2(s0, __float_as_int(f0));
                            g_pair[base + k1] = make_int2(s1, __float_as_int(f1));
                        }
                        float4 a0 = __ldg((const float4*)(Aold + (s0 << 5) + c4));
                        float4 a1 = __ldg((const float4*)(Aold + (s1 << 5) + c4));
                        mx  = fmaxf(mx,  fmaf(f0, fw4.x, a0.x));
                        my  = fmaxf(my,  fmaf(f0, fw4.y, a0.y));
                        mz  = fmaxf(mz,  fmaf(f0, fw4.z, a0.z));
                        mw2 = fmaxf(mw2, fmaf(f0, fw4.w, a0.w));
                        mx  = fmaxf(mx,  fmaf(f1, fw4.x, a1.x));
                        my  = fmaxf(my,  fmaf(f1, fw4.y, a1.y));
                        mz  = fmaxf(mz,  fmaf(f1, fw4.z, a1.z));
                        mw2 = fmaxf(mw2, fmaf(f1, fw4.w, a1.w));
                    }
                } else {
                    const int2* __restrict__ pp = g_pair + (long)n * KS8 + g;
                    int k = 0;
                    for (; k + 16 <= KS8; k += 16) {
                        int2 q0 = __ldg(pp + k);
                        int2 q1 = __ldg(pp + k + 4);
                        int2 q2 = __ldg(pp + k + 8);
                        int2 q3 = __ldg(pp + k + 12);
                        float4 a0 = __ldg((const float4*)(Aold + (q0.x << 5) + c4));
                        float4 a1 = __ldg((const float4*)(Aold + (q1.x << 5) + c4));
                        float4 a2 = __ldg((const float4*)(Aold + (q2.x << 5) + c4));
                        float4 a3 = __ldg((const float4*)(Aold + (q3.x << 5) + c4));
                        float f0 = __int_as_float(q0.y);
                        float f1 = __int_as_float(q1.y);
                        float f2 = __int_as_float(q2.y);
                        float f3 = __int_as_float(q3.y);
                        mx  = fmaxf(mx,  fmaf(f0, fw4.x, a0.x));
                        my  = fmaxf(my,  fmaf(f0, fw4.y, a0.y));
                        mz  = fmaxf(mz,  fmaf(f0, fw4.z, a0.z));
                        mw2 = fmaxf(mw2, fmaf(f0, fw4.w, a0.w));
                        mx  = fmaxf(mx,  fmaf(f1, fw4.x, a1.x));
                        my  = fmaxf(my,  fmaf(f1, fw4.y, a1.y));
                        mz  = fmaxf(mz,  fmaf(f1, fw4.z, a1.z));
                        mw2 = fmaxf(mw2, fmaf(f1, fw4.w, a1.w));
                        mx  = fmaxf(mx,  fmaf(f2, fw4.x, a2.x));
                        my  = fmaxf(my,  fmaf(f2, fw4.y, a2.y));
                        mz  = fmaxf(mz,  fmaf(f2, fw4.z, a2.z));
                        mw2 = fmaxf(mw2, fmaf(f2, fw4.w, a2.w));
                        mx  = fmaxf(mx,  fmaf(f3, fw4.x, a3.x));
                        my  = fmaxf(my,  fmaf(f3, fw4.y, a3.y));
                        mz  = fmaxf(mz,  fmaf(f3, fw4.z, a3.z));
                        mw2 = fmaxf(mw2, fmaf(f3, fw4.w, a3.w));
                    }
                    if (k < KS8) {   // 8-edge tail
                        int2 q0 = __ldg(pp + k);
                        int2 q1 = __ldg(pp + k + 4);
                        float4 a0 = __ldg((const float4*)(Aold + (q0.x << 5) + c4));
                        float4 a1 = __ldg((const float4*)(Aold + (q1.x << 5) + c4));
                        float f0 = __int_as_float(q0.y);
                        float f1 = __int_as_float(q1.y);
                        mx  = fmaxf(mx,  fmaf(f0, fw4.x, a0.x));
                        my  = fmaxf(my,  fmaf(f0, fw4.y, a0.y));
                        mz  = fmaxf(mz,  fmaf(f0, fw4.z, a0.z));
                        mw2 = fmaxf(mw2, fmaf(f0, fw4.w, a0.w));
                        mx  = fmaxf(mx,  fmaf(f1, fw4.x, a1.x));
                        my  = fmaxf(my,  fmaf(f1, fw4.y, a1.y));
                        mz  = fmaxf(mz,  fmaf(f1, fw4.z, a1.z));
                        mw2 = fmaxf(mw2, fmaf(f1, fw4.w, a1.w));
                    }
                }
                mx  = fmaxf(mx,  __shfl_xor_sync(0xffffffffu, mx, 8));
                my  = fmaxf(my,  __shfl_xor_sync(0xffffffffu, my, 8));
                mz  = fmaxf(mz,  __shfl_xor_sync(0xffffffffu, mz, 8));
                mw2 = fmaxf(mw2, __shfl_xor_sync(0xffffffffu, mw2, 8));
                mx  = fmaxf(mx,  __shfl_xor_sync(0xffffffffu, mx, 16));
                my  = fmaxf(my,  __shfl_xor_sync(0xffffffffu, my, 16));
                mz  = fmaxf(mz,  __shfl_xor_sync(0xffffffffu, mz, 16));
                mw2 = fmaxf(mw2, __shfl_xor_sync(0xffffffffu, mw2, 16));
                if (g == 0)
                    *(float4*)&s_um[w][qi * 32 + c4] = make_float4(mx, my, mz, mw2);
            }
            __syncwarp();

            // ---------------- node phase (z, Bc in registers) ---------------
            float u0 = bc0 + s_um[w][j];
            float u1 = bc1 + s_um[w][32 + j];
            s_zs[j][qb + 0] = z0; s_zs[j][qb + 1] = z1;
            s_us[j][qb + 0] = u0; s_us[j][qb + 1] = u1;
            __syncwarp();
            float ub = __ldg(Ub + j);
            float nh0 = ub, nh1 = ub;
            #pragma unroll
            for (int i = 0; i < HID; i++) {
                float wz = s_Uw[i * HID + j], wu = s_Uw[(HID + i) * HID + j];
                float2 zq = *(const float2*)&s_zs[i][qb];
                float2 uq = *(const float2*)&s_us[i][qb];
                nh0 = fmaf(zq.x, wz, nh0); nh0 = fmaf(uq.x, wu, nh0);
                nh1 = fmaf(zq.y, wz, nh1); nh1 = fmaf(uq.y, wu, nh1);
            }
            float tw = s_termw[j], d1 = s_dnw[j], d2 = s_dnw[HID + j];
            float e1 = s_duw[j], e2 = s_duw[HID + j];
            float l0 = nh0 * tw, l1 = nh1 * tw;
            float qd0 = fmaf(nh0, d1, z0 * d2), qd1 = fmaf(nh1, d1, z1 * d2);
            float rd0 = fmaf(nh0, e1, z0 * e2), rd1 = fmaf(nh1, e1, z1 * e2);
            #pragma unroll
            for (int o = 16; o; o >>= 1) {
                l0  += __shfl_xor_sync(0xffffffffu, l0, o);
                l1  += __shfl_xor_sync(0xffffffffu, l1, o);
                qd0 += __shfl_xor_sync(0xffffffffu, qd0, o);
                qd1 += __shfl_xor_sync(0xffffffffu, qd1, o);
                rd0 += __shfl_xor_sync(0xffffffffu, rd0, o);
                rd1 += __shfl_xor_sync(0xffffffffu, rd1, o);
            }
            locmax = fmaxf(l0, l1) + __ldg(termb);
            float db = __ldg(dnb), du0 = __ldg(dub), dw64 = s_duw[64];
            float nn0 = qd0 + db, nn1 = qd1 + db;
            float ns0 = fmaf(nn0, dw64, rd0 + du0);
            float ns1 = fmaf(nn1, dw64, rd1 + du0);
            if (j < 2) {
                float nsv = (j == 0) ? ns0 : ns1;
                float nnv = (j == 0) ? nn0 : nn1;
                out[(t + 1) * N + n0 + j] = nsv;                  // preds
                out[T * N + T + (n0 + j) * (T - 1) + t] = nnv;    // preds_nextnode
            }
            if (!lastStep) {
                s_zs[j][qb + 0] = nh0; s_zs[j][qb + 1] = nh1;
                __syncwarp();
                const float2 p2 = *(const float2*)(pri + n0);
                float eb = __ldg(encb + j);
                float ew0 = s_encw[j], ew33 = s_encw[33 * HID + j];
                float zn0 = fmaf(ns0, ew0, fmaf(p2.x, ew33, eb));
                float zn1 = fmaf(ns1, ew0, fmaf(p2.y, ew33, eb));
                #pragma unroll
                for (int i = 0; i < HID; i++) {
                    float we = s_encw[(1 + i) * HID + j];
                    float2 hq = *(const float2*)&s_zs[i][qb];
                    zn0 = fmaf(hq.x, we, zn0); zn1 = fmaf(hq.y, we, zn1);
                }
                s_us[j][qb + 0] = zn0; s_us[j][qb + 1] = zn1;
                __syncwarp();
                float A0 = 0, A1 = 0, B0 = 0, B1 = 0;
                #pragma unroll
                for (int i = 0; i < HID; i++) {
                    float wa = s_Mw[i * HID + j], wb = s_Mw[(HID + i) * HID + j];
                    float2 zq = *(const float2*)&s_us[i][qb];
                    A0 = fmaf(zq.x, wa, A0); B0 = fmaf(zq.x, wb, B0);
                    A1 = fmaf(zq.y, wa, A1); B1 = fmaf(zq.y, wb, B1);
                }
                float mb = __ldg(Mb + j);
                float* __restrict__ Anew = g_A[(t & 1) ^ 1];
                int r = n0 * HID + j;
                Anew[r] = A0; Anew[r + HID] = A1;
                z0 = zn0; z1 = zn1;
                bc0 = B0 + mb; bc1 = B1 + mb;
            }
        }

        if (j == 0) s_red[w] = active ? locmax : -INFINITY;
        __syncthreads();
        if (tid == 0) {
            float m = -INFINITY;
            #pragma unroll
            for (int ww = 0; ww < 8; ww++) m = fmaxf(m, s_red[ww]);
            g_blockmax[t * 1024 + blockIdx.x] = m;
        }
        if (!lastStep) grid_sync_dev();
    }

    // ---------------- finalize (folded k_final) -----------------------------
    grid_sync_dev();
    if (blockIdx.x < (unsigned)(T - 1)) {
        int t = blockIdx.x;
        float m = -INFINITY;
        for (int b = tid; b < gridDim.x; b += 256)
            m = fmaxf(m, g_blockmax[t * 1024 + b]);
        s_fin[tid] = m;
        __syncthreads();
        for (int s = 128; s; s >>= 1) {
            if (tid < s) s_fin[tid] = fmaxf(s_fin[tid], s_fin[tid + s]);
            __syncthreads();
        }
        if (tid == 0) {
            float v = s_fin[0];
            out[T * N + 1 + t] = 1.0f / (1.0f + expf(-v));
            if (t == 0) out[T * N] = 0.0f;
        }
    }
}

// ---------------------------------------------------------------------------
extern "C" void kernel_launch(void* const* d_in, const int* in_sizes, int n_in,
                              void* d_out, int out_size) {
    const float* states   = (const float*)d_in[0];
    const float* priority = (const float*)d_in[1];
    const float* edges    = (const float*)d_in[2];
    const int*   src      = (const int*)d_in[3];
    const float* enc_w    = (const float*)d_in[5];
    const float* enc_b    = (const float*)d_in[6];
    const float* M_w      = (const float*)d_in[7];
    const float* M_b      = (const float*)d_in[8];
    const float* U_w      = (const float*)d_in[9];
    const float* U_b      = (const float*)d_in[10];
    const float* dn_w     = (const float*)d_in[11];
    const float* dn_b     = (const float*)d_in[12];
    const float* du_w     = (const float*)d_in[13];
    const float* du_b     = (const float*)d_in[14];
    const float* term_w   = (const float*)d_in[15];
    const float* term_b   = (const float*)d_in[16];
    float* out = (float*)d_out;

    int N = in_sizes[1];
    int E = in_sizes[3];
    int T = in_sizes[0] / N;
    int Kc = E / N;
    int Erem = E - Kc * N;
    int KS = Kc + (Erem ? 1 : 0);
    int KS8 = (KS + 7) & ~7;          // pad to multiple of 8

    int nb = (N + 15) / 16;           // 625 for N=10000; all resident (<=740)
    k_all<<<nb, 256>>>(states, priority, edges, src, enc_w, enc_b, M_w, M_b,
                       U_w, U_b, dn_w, dn_b, du_w, du_b,
                       term_w, term_b, out, N, T, KS8, Kc, Erem);
}